// round 1
// baseline (speedup 1.0000x reference)
#include <cuda_runtime.h>
#include <cuda_bf16.h>
#include <math.h>

// ---------------------------------------------------------------------------
// LSA: spectral-normed QKV proj -> dense (band-masked-out) attention -> out proj
// B=2, S=2048, D=512, H=8, Dh=64, inner=512, WINDOW=8
// Reference masks the causal band [0 <= i-j <= 7] with -FLT_MAX, softmaxes the rest.
// ---------------------------------------------------------------------------

#define BATCH 2
#define SEQ   2048
#define DMODEL 512
#define NHEADS 8
#define DHEAD 64
#define INNER 512
#define QKV3  1536
#define MROWS (BATCH*SEQ)   // 4096

// Scratch (device globals; allocation is forbidden)
__device__ float g_qkv[BATCH * SEQ * QKV3];     // [b,s,1536]
__device__ float g_attn[BATCH * SEQ * INNER];   // [b,s,512]
__device__ float g_t[2048];                     // row dots for both weights
__device__ float g_part[32];                    // per-block ||W^T t||^2 partials
__device__ float g_scales[2];                   // qkv scale, out scale

// ---------------------------------------------------------------------------
// Spectral norm:  sigma_w = ||W^T (W u)|| / ||W u||   (exact per reference math)
// scale = sigma_in / sigma_w ; applied to GEMM outputs.
// ---------------------------------------------------------------------------

// pass1: g_t[r] = dot(W[r,:], u).  blocks 0..1535 -> W_qkv, 1536..2047 -> W_out
__global__ __launch_bounds__(128)
void sn_rowdot(const float* __restrict__ Wq, const float* __restrict__ uq,
               const float* __restrict__ Wo, const float* __restrict__ uo)
{
    int rb = blockIdx.x;
    const float* W; const float* u; int row;
    if (rb < 1536) { W = Wq; u = uq; row = rb; }
    else           { W = Wo; u = uo; row = rb - 1536; }
    const float* wr = W + (size_t)row * 512;
    float s = 0.f;
    for (int c = threadIdx.x; c < 512; c += 128) s += wr[c] * u[c];
    #pragma unroll
    for (int o = 16; o >= 1; o >>= 1) s += __shfl_xor_sync(0xffffffffu, s, o);
    __shared__ float red[4];
    if ((threadIdx.x & 31) == 0) red[threadIdx.x >> 5] = s;
    __syncthreads();
    if (threadIdx.x == 0) g_t[rb] = red[0] + red[1] + red[2] + red[3];
}

// pass2: column dots s_d = sum_r W[r,d]*t[r]; accumulate ||s||^2 per 32-col block.
// blocks 0..15 -> W_qkv (R=1536), 16..31 -> W_out (R=512)
__global__ __launch_bounds__(256)
void sn_coldot(const float* __restrict__ Wq, const float* __restrict__ Wo)
{
    int blk = blockIdx.x;
    int w = blk >> 4;
    int cblk = blk & 15;
    const float* W = w ? Wo : Wq;
    int R = w ? 512 : 1536;
    int toff = w ? 1536 : 0;
    int dl = threadIdx.x & 31;
    int rg = threadIdx.x >> 5;    // 0..7
    int d = cblk * 32 + dl;
    float s = 0.f;
    for (int r = rg; r < R; r += 8) s += W[(size_t)r * 512 + d] * g_t[toff + r];
    __shared__ float red[8][33];
    red[rg][dl] = s;
    __syncthreads();
    if (rg == 0) {
        float cs = 0.f;
        #pragma unroll
        for (int q = 0; q < 8; ++q) cs += red[q][dl];
        cs = cs * cs;
        #pragma unroll
        for (int o = 16; o >= 1; o >>= 1) cs += __shfl_xor_sync(0xffffffffu, cs, o);
        if (dl == 0) g_part[blk] = cs;
    }
}

// pass3: finalize scales.  block 0 -> qkv, block 1 -> out
__global__ __launch_bounds__(256)
void sn_scale(const float* __restrict__ sq, const float* __restrict__ so)
{
    int w = blockIdx.x;
    int tid = threadIdx.x;
    float ssq = (tid < 16) ? g_part[w * 16 + tid] : 0.f;
    int R = w ? 512 : 1536;
    int off = w ? 1536 : 0;
    float tt = 0.f;
    for (int r = tid; r < R; r += 256) { float v = g_t[off + r]; tt += v * v; }
    __shared__ float ra[256], rb[256];
    ra[tid] = ssq; rb[tid] = tt;
    __syncthreads();
    for (int sft = 128; sft >= 1; sft >>= 1) {
        if (tid < sft) { ra[tid] += ra[tid + sft]; rb[tid] += rb[tid + sft]; }
        __syncthreads();
    }
    if (tid == 0) {
        float sigma_w = sqrtf(ra[0] / rb[0]);
        g_scales[w] = (w ? so[0] : sq[0]) / sigma_w;
    }
}

// ---------------------------------------------------------------------------
// GEMM: C[M,N] = (A[M,K] @ B[N,K]^T) * g_scales[scale_idx] (+ bias[n])
// 64x64 tile, 256 threads, 4x4 microtile, k-chunk 16, float4 smem reads.
// Requires M%64==0, N%64==0, K%16==0 (true here).
// ---------------------------------------------------------------------------
__global__ __launch_bounds__(256)
void gemm64(const float* __restrict__ A, const float* __restrict__ B,
            float* __restrict__ C, int M, int N, int K,
            int scale_idx, const float* __restrict__ bias)
{
    __shared__ __align__(16) float AsT[16 * 68];   // [kk][r]
    __shared__ __align__(16) float BsT[16 * 68];   // [kk][c]
    const int t = threadIdx.x;
    const int tr = t >> 4, tc = t & 15;
    const int row0 = blockIdx.y << 6, col0 = blockIdx.x << 6;
    const int lr = t >> 2, lq = t & 3;

    const float* Ap = A + (size_t)(row0 + lr) * K + (lq << 2);
    const float* Bp = B + (size_t)(col0 + lr) * K + (lq << 2);

    float acc[4][4];
    #pragma unroll
    for (int i = 0; i < 4; ++i)
        #pragma unroll
        for (int j = 0; j < 4; ++j) acc[i][j] = 0.f;

    for (int k0 = 0; k0 < K; k0 += 16) {
        float4 av = *(const float4*)(Ap + k0);
        float4 bv = *(const float4*)(Bp + k0);
        __syncthreads();
        AsT[(lq * 4 + 0) * 68 + lr] = av.x;
        AsT[(lq * 4 + 1) * 68 + lr] = av.y;
        AsT[(lq * 4 + 2) * 68 + lr] = av.z;
        AsT[(lq * 4 + 3) * 68 + lr] = av.w;
        BsT[(lq * 4 + 0) * 68 + lr] = bv.x;
        BsT[(lq * 4 + 1) * 68 + lr] = bv.y;
        BsT[(lq * 4 + 2) * 68 + lr] = bv.z;
        BsT[(lq * 4 + 3) * 68 + lr] = bv.w;
        __syncthreads();
        #pragma unroll
        for (int kk = 0; kk < 16; ++kk) {
            float4 a4 = *(const float4*)&AsT[kk * 68 + tr * 4];
            float4 b4 = *(const float4*)&BsT[kk * 68 + tc * 4];
            acc[0][0] += a4.x * b4.x; acc[0][1] += a4.x * b4.y;
            acc[0][2] += a4.x * b4.z; acc[0][3] += a4.x * b4.w;
            acc[1][0] += a4.y * b4.x; acc[1][1] += a4.y * b4.y;
            acc[1][2] += a4.y * b4.z; acc[1][3] += a4.y * b4.w;
            acc[2][0] += a4.z * b4.x; acc[2][1] += a4.z * b4.y;
            acc[2][2] += a4.z * b4.z; acc[2][3] += a4.z * b4.w;
            acc[3][0] += a4.w * b4.x; acc[3][1] += a4.w * b4.y;
            acc[3][2] += a4.w * b4.z; acc[3][3] += a4.w * b4.w;
        }
    }
    const float scale = g_scales[scale_idx];
    float4 bv4 = make_float4(0.f, 0.f, 0.f, 0.f);
    if (bias) {
        bv4.x = bias[col0 + tc * 4 + 0];
        bv4.y = bias[col0 + tc * 4 + 1];
        bv4.z = bias[col0 + tc * 4 + 2];
        bv4.w = bias[col0 + tc * 4 + 3];
    }
    #pragma unroll
    for (int i = 0; i < 4; ++i) {
        float4 o;
        o.x = acc[i][0] * scale + bv4.x;
        o.y = acc[i][1] * scale + bv4.y;
        o.z = acc[i][2] * scale + bv4.z;
        o.w = acc[i][3] * scale + bv4.w;
        *(float4*)&C[(size_t)(row0 + tr * 4 + i) * N + col0 + tc * 4] = o;
    }
}

// ---------------------------------------------------------------------------
// Flash-style attention over full S=2048 with the 8-wide causal band masked OUT.
// Grid: (32 q-tiles, 16 batch-heads). Block 256, 64x64 Q/K tiles, 4x4 microtile.
// ---------------------------------------------------------------------------
__global__ __launch_bounds__(256)
void attn_kernel(const float* __restrict__ qkv,
                 const float* __restrict__ temp,
                 float* __restrict__ out)
{
    extern __shared__ __align__(16) float sm[];
    float* QsT = sm;                 // [d][r] stride 68
    float* KsT = sm + 64 * 68;       // [d][j] stride 68
    float* Vs  = sm + 2 * 64 * 68;   // [j][d] stride 68
    float* Ps  = sm + 3 * 64 * 68;   // [r][j] stride 68

    const int t  = threadIdx.x;
    const int tr = t >> 4;           // 0..15
    const int tc = t & 15;           // 0..15
    const int bh = blockIdx.y;
    const int b  = bh >> 3;
    const int h  = bh & 7;
    const int s0 = blockIdx.x << 6;

    const float dscale = expf(temp[0]);  // exp(log(Dh^-0.5)) = 0.125

    const float* base = qkv + (size_t)b * SEQ * QKV3 + h * DHEAD;

    // Q tile, transposed: QsT[d][r] = q[s0+r][d]
    #pragma unroll
    for (int it = 0; it < 16; ++it) {
        int idx = t + it * 256;
        int r = idx >> 6;
        int d = idx & 63;
        QsT[d * 68 + r] = base[(size_t)(s0 + r) * QKV3 + d];
    }

    float m[4], l[4], oacc[4][4];
    #pragma unroll
    for (int i = 0; i < 4; ++i) {
        m[i] = -1e30f; l[i] = 0.f;
        #pragma unroll
        for (int j = 0; j < 4; ++j) oacc[i][j] = 0.f;
    }

    for (int kt = 0; kt < SEQ / 64; ++kt) {
        const int j0 = kt << 6;
        __syncthreads();   // previous iter's reads of KsT/Vs done
        #pragma unroll
        for (int it = 0; it < 16; ++it) {
            int idx = t + it * 256;
            int r = idx >> 6;
            int d = idx & 63;
            const float* rp = base + (size_t)(j0 + r) * QKV3;
            KsT[d * 68 + r] = rp[512 + d];
            Vs[r * 68 + d]  = rp[1024 + d];
        }
        __syncthreads();

        // S = Q K^T  (4x4 per thread)
        float sacc[4][4];
        #pragma unroll
        for (int i = 0; i < 4; ++i)
            #pragma unroll
            for (int j = 0; j < 4; ++j) sacc[i][j] = 0.f;

        #pragma unroll 8
        for (int d = 0; d < 64; ++d) {
            float4 qa = *(const float4*)&QsT[d * 68 + tr * 4];
            float4 kb = *(const float4*)&KsT[d * 68 + tc * 4];
            sacc[0][0] += qa.x * kb.x; sacc[0][1] += qa.x * kb.y;
            sacc[0][2] += qa.x * kb.z; sacc[0][3] += qa.x * kb.w;
            sacc[1][0] += qa.y * kb.x; sacc[1][1] += qa.y * kb.y;
            sacc[1][2] += qa.y * kb.z; sacc[1][3] += qa.y * kb.w;
            sacc[2][0] += qa.z * kb.x; sacc[2][1] += qa.z * kb.y;
            sacc[2][2] += qa.z * kb.z; sacc[2][3] += qa.z * kb.w;
            sacc[3][0] += qa.w * kb.x; sacc[3][1] += qa.w * kb.y;
            sacc[3][2] += qa.w * kb.z; sacc[3][3] += qa.w * kb.w;
        }

        // scale + band mask + online softmax.
        // Row r is shared by the 16 lanes with the same tr (within one warp:
        // lane = (tr&1)*16 + tc), so shfl_xor over {1,2,4,8} reduces the row.
        const int gi0 = s0 + tr * 4;
        const int gj0 = j0 + tc * 4;
        #pragma unroll
        for (int i = 0; i < 4; ++i) {
            const int gi = gi0 + i;
            float p[4];
            float tmax = -1e30f;
            #pragma unroll
            for (int jj = 0; jj < 4; ++jj) {
                int diff = gi - (gj0 + jj);
                float v = sacc[i][jj] * dscale;
                if (diff >= 0 && diff < 8) v = -1e30f;   // masked-OUT band
                p[jj] = v;
                tmax = fmaxf(tmax, v);
            }
            #pragma unroll
            for (int o = 8; o >= 1; o >>= 1)
                tmax = fmaxf(tmax, __shfl_xor_sync(0xffffffffu, tmax, o));
            float mn = fmaxf(m[i], tmax);
            float corr = expf(m[i] - mn);
            m[i] = mn;
            float ps = 0.f;
            #pragma unroll
            for (int jj = 0; jj < 4; ++jj) {
                float pv = expf(p[jj] - mn);   // masked: exp(-1e30) == 0
                ps += pv;
                Ps[(tr * 4 + i) * 68 + tc * 4 + jj] = pv;
            }
            #pragma unroll
            for (int o = 8; o >= 1; o >>= 1)
                ps += __shfl_xor_sync(0xffffffffu, ps, o);
            l[i] = l[i] * corr + ps;
            #pragma unroll
            for (int jj = 0; jj < 4; ++jj) oacc[i][jj] *= corr;
        }
        __syncwarp();   // Ps row produced & consumed within the same warp

        // O += P @ V   (thread owns rows tr*4+i, dims tc*4..+3)
        #pragma unroll 8
        for (int j = 0; j < 64; ++j) {
            float4 vv = *(const float4*)&Vs[j * 68 + tc * 4];
            #pragma unroll
            for (int i = 0; i < 4; ++i) {
                float pv = Ps[(tr * 4 + i) * 68 + j];
                oacc[i][0] += pv * vv.x;
                oacc[i][1] += pv * vv.y;
                oacc[i][2] += pv * vv.z;
                oacc[i][3] += pv * vv.w;
            }
        }
    }

    // epilogue: out[b][s0+r][h*64+d] = oacc / l
    float* ob = out + ((size_t)b * SEQ + s0) * INNER + h * DHEAD;
    #pragma unroll
    for (int i = 0; i < 4; ++i) {
        float inv = 1.f / l[i];
        float4 o4;
        o4.x = oacc[i][0] * inv;
        o4.y = oacc[i][1] * inv;
        o4.z = oacc[i][2] * inv;
        o4.w = oacc[i][3] * inv;
        *(float4*)&ob[(size_t)(tr * 4 + i) * INNER + tc * 4] = o4;
    }
}

// ---------------------------------------------------------------------------
extern "C" void kernel_launch(void* const* d_in, const int* in_sizes, int n_in,
                              void* d_out, int out_size)
{
    const float* x    = (const float*)d_in[0];
    const float* Wq   = (const float*)d_in[1];
    const float* uq   = (const float*)d_in[2];
    const float* sq   = (const float*)d_in[3];
    const float* Wo   = (const float*)d_in[4];
    const float* bo   = (const float*)d_in[5];
    const float* uo   = (const float*)d_in[6];
    const float* so   = (const float*)d_in[7];
    const float* temp = (const float*)d_in[8];

    float* p_qkv  = nullptr;
    float* p_attn = nullptr;
    cudaGetSymbolAddress((void**)&p_qkv,  g_qkv);
    cudaGetSymbolAddress((void**)&p_attn, g_attn);

    // spectral-norm scale factors (both weights)
    sn_rowdot<<<2048, 128>>>(Wq, uq, Wo, uo);
    sn_coldot<<<32, 256>>>(Wq, Wo);
    sn_scale<<<2, 256>>>(sq, so);

    // qkv = (x @ W_qkv^T) * scale_qkv
    gemm64<<<dim3(QKV3 / 64, MROWS / 64), 256>>>(
        x, Wq, p_qkv, MROWS, QKV3, DMODEL, 0, (const float*)nullptr);

    // attention
    int smem = 4 * 64 * 68 * (int)sizeof(float);   // 69632 B
    cudaFuncSetAttribute(attn_kernel, cudaFuncAttributeMaxDynamicSharedMemorySize, smem);
    attn_kernel<<<dim3(SEQ / 64, BATCH * NHEADS), 256, smem>>>(p_qkv, temp, p_attn);

    // out = (attn @ W_out^T) * scale_out + b_out
    gemm64<<<dim3(DMODEL / 64, MROWS / 64), 256>>>(
        p_attn, Wo, (float*)d_out, MROWS, DMODEL, INNER, 1, bo);
}

// round 2
// speedup vs baseline: 2.9087x; 2.9087x over previous
#include <cuda_runtime.h>
#include <math.h>

#define BATCH 2
#define SEQ   2048
#define DMODEL 512
#define NHEADS 8
#define DHEAD 64
#define INNER 512
#define QKV3  1536
#define MROWS (BATCH*SEQ)   // 4096

// Scratch (device globals; allocation is forbidden)
__device__ float g_qkv[BATCH * SEQ * QKV3];     // [b,s,1536]
__device__ float g_attn[BATCH * SEQ * INNER];   // [b,s,512]
__device__ float g_t[2048];
__device__ float g_part[32];
__device__ float g_scales[2];

// ---------------------------------------------------------------------------
// tf32 helpers
// ---------------------------------------------------------------------------
__device__ __forceinline__ unsigned f2tf(float x) {
    unsigned r;
    asm("cvt.rna.tf32.f32 %0, %1;" : "=r"(r) : "f"(x));
    return r;
}

__device__ __forceinline__ void mma8(float* c, const unsigned* a, const unsigned* b) {
    asm volatile(
        "mma.sync.aligned.m16n8k8.row.col.f32.tf32.tf32.f32 "
        "{%0,%1,%2,%3}, {%4,%5,%6,%7}, {%8,%9}, {%0,%1,%2,%3};"
        : "+f"(c[0]), "+f"(c[1]), "+f"(c[2]), "+f"(c[3])
        : "r"(a[0]), "r"(a[1]), "r"(a[2]), "r"(a[3]), "r"(b[0]), "r"(b[1]));
}

// fast 2^y on the FMA pipe (no MUFU). y <= 0 expected; clamped at -80 so that
// masked (-1e30) logits underflow to ~8e-25 instead of producing garbage.
__device__ __forceinline__ float exp2c(float y) {
    y = fmaxf(y, -80.0f);
    float z = y + 12582912.0f;          // 1.5*2^23: round-to-nearest-int trick
    int   n = __float_as_int(z);        // low bits hold round(y)
    float f = y - (z - 12582912.0f);    // f in [-0.5, 0.5]
    float p = 1.3333558e-3f;
    p = fmaf(p, f, 9.6181291e-3f);
    p = fmaf(p, f, 5.5504109e-2f);
    p = fmaf(p, f, 2.4022651e-1f);
    p = fmaf(p, f, 6.9314718e-1f);
    p = fmaf(p, f, 1.0f);
    return __int_as_float(__float_as_int(p) + (n << 23));
}

// ---------------------------------------------------------------------------
// Spectral norm: sigma_w = ||W^T (Wu/||Wu||)||, scale = sigma_in / sigma_w
// ---------------------------------------------------------------------------
__global__ __launch_bounds__(128)
void sn_rowdot(const float* __restrict__ Wq, const float* __restrict__ uq,
               const float* __restrict__ Wo, const float* __restrict__ uo)
{
    int rb = blockIdx.x;
    const float* W; const float* u; int row;
    if (rb < 1536) { W = Wq; u = uq; row = rb; }
    else           { W = Wo; u = uo; row = rb - 1536; }
    const float* wr = W + (size_t)row * 512;
    float s = 0.f;
    for (int c = threadIdx.x; c < 512; c += 128) s += wr[c] * u[c];
    #pragma unroll
    for (int o = 16; o >= 1; o >>= 1) s += __shfl_xor_sync(0xffffffffu, s, o);
    __shared__ float red[4];
    if ((threadIdx.x & 31) == 0) red[threadIdx.x >> 5] = s;
    __syncthreads();
    if (threadIdx.x == 0) g_t[rb] = red[0] + red[1] + red[2] + red[3];
}

__global__ __launch_bounds__(256)
void sn_coldot(const float* __restrict__ Wq, const float* __restrict__ Wo)
{
    int blk = blockIdx.x;
    int w = blk >> 4;
    int cblk = blk & 15;
    const float* W = w ? Wo : Wq;
    int R = w ? 512 : 1536;
    int toff = w ? 1536 : 0;
    int dl = threadIdx.x & 31;
    int rg = threadIdx.x >> 5;
    int d = cblk * 32 + dl;
    float s = 0.f;
    for (int r = rg; r < R; r += 8) s += W[(size_t)r * 512 + d] * g_t[toff + r];
    __shared__ float red[8][33];
    red[rg][dl] = s;
    __syncthreads();
    if (rg == 0) {
        float cs = 0.f;
        #pragma unroll
        for (int q = 0; q < 8; ++q) cs += red[q][dl];
        cs = cs * cs;
        #pragma unroll
        for (int o = 16; o >= 1; o >>= 1) cs += __shfl_xor_sync(0xffffffffu, cs, o);
        if (dl == 0) g_part[blk] = cs;
    }
}

__global__ __launch_bounds__(256)
void sn_scale(const float* __restrict__ sq, const float* __restrict__ so)
{
    int w = blockIdx.x;
    int tid = threadIdx.x;
    float ssq = (tid < 16) ? g_part[w * 16 + tid] : 0.f;
    int R = w ? 512 : 1536;
    int off = w ? 1536 : 0;
    float tt = 0.f;
    for (int r = tid; r < R; r += 256) { float v = g_t[off + r]; tt += v * v; }
    __shared__ float ra[256], rb[256];
    ra[tid] = ssq; rb[tid] = tt;
    __syncthreads();
    for (int sft = 128; sft >= 1; sft >>= 1) {
        if (tid < sft) { ra[tid] += ra[tid + sft]; rb[tid] += rb[tid + sft]; }
        __syncthreads();
    }
    if (tid == 0) {
        float sigma_w = sqrtf(ra[0] / rb[0]);
        g_scales[w] = (w ? so[0] : sq[0]) / sigma_w;
    }
}

// ---------------------------------------------------------------------------
// tf32 tensor-core GEMM: C[M,N] = (A[M,K] @ B[N,K]^T) * g_scales[si] (+bias)
// Block 256 thr (8 warps, 2x4), tile 128x128, K-step 32, warp tile 64x32.
// M%128==0, N%128==0, K%32==0 required (holds: 4096 x {1536,512} x 512).
// ---------------------------------------------------------------------------
__global__ __launch_bounds__(256)
void gemm_tf32(const float* __restrict__ A, const float* __restrict__ B,
               float* __restrict__ C, int M, int N, int K,
               int scale_idx, const float* __restrict__ bias)
{
    __shared__ unsigned As[128 * 36];
    __shared__ unsigned Bs[128 * 36];
    const int t    = threadIdx.x;
    const int lane = t & 31;
    const int wid  = t >> 5;
    const int g  = lane >> 2;       // 0..7
    const int tg = lane & 3;        // 0..3
    const int wm = (wid >> 2) * 64; // 0 / 64
    const int wn = (wid & 3) * 32;  // 0/32/64/96
    const int row0 = blockIdx.y * 128;
    const int col0 = blockIdx.x * 128;

    float acc[4][4][4];
    #pragma unroll
    for (int mi = 0; mi < 4; ++mi)
        #pragma unroll
        for (int ni = 0; ni < 4; ++ni)
            #pragma unroll
            for (int r = 0; r < 4; ++r) acc[mi][ni][r] = 0.f;

    for (int k0 = 0; k0 < K; k0 += 32) {
        __syncthreads();
        #pragma unroll
        for (int i = 0; i < 4; ++i) {
            int idx = t + i * 256;
            int r   = idx >> 3;
            int c4  = (idx & 7) * 4;
            float4 av = *(const float4*)&A[(size_t)(row0 + r) * K + k0 + c4];
            float4 bv = *(const float4*)&B[(size_t)(col0 + r) * K + k0 + c4];
            unsigned* pa = &As[r * 36 + c4];
            pa[0] = f2tf(av.x); pa[1] = f2tf(av.y); pa[2] = f2tf(av.z); pa[3] = f2tf(av.w);
            unsigned* pb = &Bs[r * 36 + c4];
            pb[0] = f2tf(bv.x); pb[1] = f2tf(bv.y); pb[2] = f2tf(bv.z); pb[3] = f2tf(bv.w);
        }
        __syncthreads();
        #pragma unroll
        for (int ki = 0; ki < 4; ++ki) {
            const int kk = ki * 8;
            unsigned af[4][4], bf[4][2];
            #pragma unroll
            for (int mi = 0; mi < 4; ++mi) {
                int r = wm + mi * 16;
                af[mi][0] = As[(r + g) * 36 + kk + tg];
                af[mi][1] = As[(r + g + 8) * 36 + kk + tg];
                af[mi][2] = As[(r + g) * 36 + kk + tg + 4];
                af[mi][3] = As[(r + g + 8) * 36 + kk + tg + 4];
            }
            #pragma unroll
            for (int ni = 0; ni < 4; ++ni) {
                int c = wn + ni * 8;
                bf[ni][0] = Bs[(c + g) * 36 + kk + tg];
                bf[ni][1] = Bs[(c + g) * 36 + kk + tg + 4];
            }
            #pragma unroll
            for (int mi = 0; mi < 4; ++mi)
                #pragma unroll
                for (int ni = 0; ni < 4; ++ni)
                    mma8(acc[mi][ni], af[mi], bf[ni]);
        }
    }

    const float scale = g_scales[scale_idx];
    #pragma unroll
    for (int mi = 0; mi < 4; ++mi) {
        int r = row0 + wm + mi * 16 + g;
        #pragma unroll
        for (int ni = 0; ni < 4; ++ni) {
            int c = col0 + wn + ni * 8 + tg * 2;
            float b0 = 0.f, b1 = 0.f;
            if (bias) { b0 = bias[c]; b1 = bias[c + 1]; }
            float2 lo, hi;
            lo.x = acc[mi][ni][0] * scale + b0;
            lo.y = acc[mi][ni][1] * scale + b1;
            hi.x = acc[mi][ni][2] * scale + b0;
            hi.y = acc[mi][ni][3] * scale + b1;
            *(float2*)&C[(size_t)r * N + c]       = lo;
            *(float2*)&C[(size_t)(r + 8) * N + c] = hi;
        }
    }
}

// ---------------------------------------------------------------------------
// Flash attention, tf32 mma + poly exp2 softmax.
// Block 256 thr (8 warps), Bq=128 rows (warp w -> rows w*16..+15), Bk=64.
// Grid (SEQ/128, B*H). Band [0 <= i-j <= 7] is masked OUT (per reference).
// ---------------------------------------------------------------------------
__global__ __launch_bounds__(256)
void attn_tf32(const float* __restrict__ qkv,
               const float* __restrict__ temp,
               float* __restrict__ out)
{
    extern __shared__ unsigned sm[];
    unsigned* Ks = sm;                       // [64][68]
    unsigned* Vs = sm + 64 * 68;             // [64][72]
    unsigned* Ps = sm + 64 * 68 + 64 * 72;   // [128][68]  (also Q staging)

    const int t    = threadIdx.x;
    const int lane = t & 31;
    const int w    = t >> 5;        // warp 0..7
    const int g    = lane >> 2;     // 0..7
    const int tg   = lane & 3;      // 0..3
    const int bh = blockIdx.y;
    const int b  = bh >> 3;
    const int h  = bh & 7;
    const int s0 = blockIdx.x * 128;
    const int rb = w * 16;

    const float k2 = __expf(temp[0]) * 1.4426950408889634f; // exp(T)*log2(e)
    const float* base = qkv + (size_t)b * SEQ * QKV3 + h * DHEAD;

    // stage Q tile [128][64] (tf32) into Ps, pull per-warp fragments to regs
    #pragma unroll
    for (int i = 0; i < 8; ++i) {
        int idx = t + i * 256;
        int r   = idx >> 4;
        int c4  = (idx & 15) * 4;
        float4 v = *(const float4*)&base[(size_t)(s0 + r) * QKV3 + c4];
        unsigned* p = &Ps[r * 68 + c4];
        p[0] = f2tf(v.x); p[1] = f2tf(v.y); p[2] = f2tf(v.z); p[3] = f2tf(v.w);
    }
    __syncthreads();
    unsigned qf[8][4];
    #pragma unroll
    for (int ki = 0; ki < 8; ++ki) {
        int kk = ki * 8;
        qf[ki][0] = Ps[(rb + g) * 68 + kk + tg];
        qf[ki][1] = Ps[(rb + g + 8) * 68 + kk + tg];
        qf[ki][2] = Ps[(rb + g) * 68 + kk + tg + 4];
        qf[ki][3] = Ps[(rb + g + 8) * 68 + kk + tg + 4];
    }
    // Ps rows of warp w are only ever read/written by warp w afterwards.

    float o[8][4];
    #pragma unroll
    for (int df = 0; df < 8; ++df) { o[df][0] = o[df][1] = o[df][2] = o[df][3] = 0.f; }
    float m2lo = -1e30f, m2hi = -1e30f, llo = 0.f, lhi = 0.f;

    for (int kt = 0; kt < SEQ / 64; ++kt) {
        const int j0 = kt * 64;
        __syncthreads();   // prior reads of Ks/Vs complete
        #pragma unroll
        for (int i = 0; i < 4; ++i) {
            int idx = t + i * 256;
            int r   = idx >> 4;
            int c4  = (idx & 15) * 4;
            const float* rp = &base[(size_t)(j0 + r) * QKV3 + c4];
            float4 kv = *(const float4*)(rp + 512);
            float4 vv = *(const float4*)(rp + 1024);
            unsigned* pk = &Ks[r * 68 + c4];
            pk[0] = f2tf(kv.x); pk[1] = f2tf(kv.y); pk[2] = f2tf(kv.z); pk[3] = f2tf(kv.w);
            unsigned* pv = &Vs[r * 72 + c4];
            pv[0] = f2tf(vv.x); pv[1] = f2tf(vv.y); pv[2] = f2tf(vv.z); pv[3] = f2tf(vv.w);
        }
        __syncthreads();

        // S = Q @ K^T  (warp tile 16 x 64)
        float s[8][4];
        #pragma unroll
        for (int ni = 0; ni < 8; ++ni) {
            s[ni][0] = s[ni][1] = s[ni][2] = s[ni][3] = 0.f;
            #pragma unroll
            for (int ki = 0; ki < 8; ++ki) {
                unsigned bf[2];
                bf[0] = Ks[(ni * 8 + g) * 68 + ki * 8 + tg];
                bf[1] = Ks[(ni * 8 + g) * 68 + ki * 8 + tg + 4];
                mma8(s[ni], qf[ki], bf);
            }
        }

        // scale (base-2) + band mask + row max
        const int rlo = s0 + rb + g;
        const int rhi = rlo + 8;
        float mxlo = -1e30f, mxhi = -1e30f;
        #pragma unroll
        for (int ni = 0; ni < 8; ++ni) {
            int c = j0 + ni * 8 + tg * 2;
            #pragma unroll
            for (int jj = 0; jj < 2; ++jj) {
                int cc = c + jj;
                float vlo = s[ni][jj] * k2;
                if ((unsigned)(rlo - cc) < 8u) vlo = -1e30f;
                s[ni][jj] = vlo;
                mxlo = fmaxf(mxlo, vlo);
                float vhi = s[ni][2 + jj] * k2;
                if ((unsigned)(rhi - cc) < 8u) vhi = -1e30f;
                s[ni][2 + jj] = vhi;
                mxhi = fmaxf(mxhi, vhi);
            }
        }
        mxlo = fmaxf(mxlo, __shfl_xor_sync(0xffffffffu, mxlo, 1));
        mxlo = fmaxf(mxlo, __shfl_xor_sync(0xffffffffu, mxlo, 2));
        mxhi = fmaxf(mxhi, __shfl_xor_sync(0xffffffffu, mxhi, 1));
        mxhi = fmaxf(mxhi, __shfl_xor_sync(0xffffffffu, mxhi, 2));

        float nmlo = fmaxf(m2lo, mxlo);
        float nmhi = fmaxf(m2hi, mxhi);
        float clo = exp2c(m2lo - nmlo);
        float chi = exp2c(m2hi - nmhi);
        m2lo = nmlo; m2hi = nmhi;

        // P = exp2(s - m), store tf32 to Ps, accumulate row sums
        float pslo = 0.f, pshi = 0.f;
        #pragma unroll
        for (int ni = 0; ni < 8; ++ni) {
            float p0 = exp2c(s[ni][0] - nmlo);
            float p1 = exp2c(s[ni][1] - nmlo);
            float p2 = exp2c(s[ni][2] - nmhi);
            float p3 = exp2c(s[ni][3] - nmhi);
            pslo += p0 + p1;
            pshi += p2 + p3;
            int c = ni * 8 + tg * 2;
            Ps[(rb + g) * 68 + c]         = f2tf(p0);
            Ps[(rb + g) * 68 + c + 1]     = f2tf(p1);
            Ps[(rb + g + 8) * 68 + c]     = f2tf(p2);
            Ps[(rb + g + 8) * 68 + c + 1] = f2tf(p3);
        }
        pslo += __shfl_xor_sync(0xffffffffu, pslo, 1);
        pslo += __shfl_xor_sync(0xffffffffu, pslo, 2);
        pshi += __shfl_xor_sync(0xffffffffu, pshi, 1);
        pshi += __shfl_xor_sync(0xffffffffu, pshi, 2);
        llo = llo * clo + pslo;
        lhi = lhi * chi + pshi;
        #pragma unroll
        for (int df = 0; df < 8; ++df) {
            o[df][0] *= clo; o[df][1] *= clo;
            o[df][2] *= chi; o[df][3] *= chi;
        }
        __syncwarp();

        // O += P @ V
        #pragma unroll
        for (int kj = 0; kj < 8; ++kj) {
            unsigned af[4];
            af[0] = Ps[(rb + g) * 68 + kj * 8 + tg];
            af[1] = Ps[(rb + g + 8) * 68 + kj * 8 + tg];
            af[2] = Ps[(rb + g) * 68 + kj * 8 + tg + 4];
            af[3] = Ps[(rb + g + 8) * 68 + kj * 8 + tg + 4];
            #pragma unroll
            for (int df = 0; df < 8; ++df) {
                unsigned bf[2];
                bf[0] = Vs[(kj * 8 + tg) * 72 + df * 8 + g];
                bf[1] = Vs[(kj * 8 + tg + 4) * 72 + df * 8 + g];
                mma8(o[df], af, bf);
            }
        }
    }

    // epilogue
    const float ilo = 1.f / llo;
    const float ihi = 1.f / lhi;
    float* ob = out + ((size_t)b * SEQ + s0 + rb) * INNER + h * DHEAD;
    #pragma unroll
    for (int df = 0; df < 8; ++df) {
        int c = df * 8 + tg * 2;
        float2 lo, hi;
        lo.x = o[df][0] * ilo; lo.y = o[df][1] * ilo;
        hi.x = o[df][2] * ihi; hi.y = o[df][3] * ihi;
        *(float2*)&ob[(size_t)g * INNER + c]       = lo;
        *(float2*)&ob[(size_t)(g + 8) * INNER + c] = hi;
    }
}

// ---------------------------------------------------------------------------
extern "C" void kernel_launch(void* const* d_in, const int* in_sizes, int n_in,
                              void* d_out, int out_size)
{
    const float* x    = (const float*)d_in[0];
    const float* Wq   = (const float*)d_in[1];
    const float* uq   = (const float*)d_in[2];
    const float* sq   = (const float*)d_in[3];
    const float* Wo   = (const float*)d_in[4];
    const float* bo   = (const float*)d_in[5];
    const float* uo   = (const float*)d_in[6];
    const float* so   = (const float*)d_in[7];
    const float* temp = (const float*)d_in[8];

    float* p_qkv  = nullptr;
    float* p_attn = nullptr;
    cudaGetSymbolAddress((void**)&p_qkv,  g_qkv);
    cudaGetSymbolAddress((void**)&p_attn, g_attn);

    // spectral-norm scale factors
    sn_rowdot<<<2048, 128>>>(Wq, uq, Wo, uo);
    sn_coldot<<<32, 256>>>(Wq, Wo);
    sn_scale<<<2, 256>>>(sq, so);

    // qkv = (x @ W_qkv^T) * scale_qkv
    gemm_tf32<<<dim3(QKV3 / 128, MROWS / 128), 256>>>(
        x, Wq, p_qkv, MROWS, QKV3, DMODEL, 0, (const float*)nullptr);

    // attention
    int smem = (64 * 68 + 64 * 72 + 128 * 68) * (int)sizeof(unsigned); // 70656
    cudaFuncSetAttribute(attn_tf32, cudaFuncAttributeMaxDynamicSharedMemorySize, smem);
    attn_tf32<<<dim3(SEQ / 128, BATCH * NHEADS), 256, smem>>>(p_qkv, temp, p_attn);

    // out = (attn @ W_out^T) * scale_out + b_out
    gemm_tf32<<<dim3(DMODEL / 128, MROWS / 128), 256>>>(
        p_attn, Wo, (float*)d_out, MROWS, DMODEL, INNER, 1, bo);
}

// round 3
// speedup vs baseline: 3.4995x; 1.2031x over previous
#include <cuda_runtime.h>
#include <math.h>

#define BATCH 2
#define SEQ   2048
#define DMODEL 512
#define NHEADS 8
#define DHEAD 64
#define INNER 512
#define QKV3  1536
#define MROWS (BATCH*SEQ)   // 4096

// Scratch (device globals; allocation is forbidden)
__device__ float g_qkv[BATCH * SEQ * QKV3];     // [b,s,1536]
__device__ float g_attn[BATCH * SEQ * INNER];   // [b,s,512]
__device__ float g_t[2048];
__device__ float g_part[32];
__device__ float g_scales[2];

// ---------------------------------------------------------------------------
// tf32 helpers
// ---------------------------------------------------------------------------
__device__ __forceinline__ unsigned f2tf(float x) {
    unsigned r;
    asm("cvt.rna.tf32.f32 %0, %1;" : "=r"(r) : "f"(x));
    return r;
}

__device__ __forceinline__ void mma8(float* c, const unsigned* a, const unsigned* b) {
    asm volatile(
        "mma.sync.aligned.m16n8k8.row.col.f32.tf32.tf32.f32 "
        "{%0,%1,%2,%3}, {%4,%5,%6,%7}, {%8,%9}, {%0,%1,%2,%3};"
        : "+f"(c[0]), "+f"(c[1]), "+f"(c[2]), "+f"(c[3])
        : "r"(a[0]), "r"(a[1]), "r"(a[2]), "r"(a[3]), "r"(b[0]), "r"(b[1]));
}

// fast 2^y on the FMA pipe. Clamped at -80 so masked (-1e30) logits underflow.
__device__ __forceinline__ float exp2c(float y) {
    y = fmaxf(y, -80.0f);
    float z = y + 12582912.0f;          // 1.5*2^23 round-to-int trick
    int   n = __float_as_int(z);
    float f = y - (z - 12582912.0f);    // f in [-0.5, 0.5]
    float p = 1.3333558e-3f;
    p = fmaf(p, f, 9.6181291e-3f);
    p = fmaf(p, f, 5.5504109e-2f);
    p = fmaf(p, f, 2.4022651e-1f);
    p = fmaf(p, f, 6.9314718e-1f);
    p = fmaf(p, f, 1.0f);
    return __int_as_float(__float_as_int(p) + (n << 23));
}

// ---------------------------------------------------------------------------
// Spectral norm: sigma_w = ||W^T (Wu/||Wu||)||, scale = sigma_in / sigma_w
// ---------------------------------------------------------------------------
__global__ __launch_bounds__(128)
void sn_rowdot(const float* __restrict__ Wq, const float* __restrict__ uq,
               const float* __restrict__ Wo, const float* __restrict__ uo)
{
    int rb = blockIdx.x;
    const float* W; const float* u; int row;
    if (rb < 1536) { W = Wq; u = uq; row = rb; }
    else           { W = Wo; u = uo; row = rb - 1536; }
    const float* wr = W + (size_t)row * 512;
    float s = 0.f;
    for (int c = threadIdx.x; c < 512; c += 128) s += wr[c] * u[c];
    #pragma unroll
    for (int o = 16; o >= 1; o >>= 1) s += __shfl_xor_sync(0xffffffffu, s, o);
    __shared__ float red[4];
    if ((threadIdx.x & 31) == 0) red[threadIdx.x >> 5] = s;
    __syncthreads();
    if (threadIdx.x == 0) g_t[rb] = red[0] + red[1] + red[2] + red[3];
}

__global__ __launch_bounds__(256)
void sn_coldot(const float* __restrict__ Wq, const float* __restrict__ Wo)
{
    int blk = blockIdx.x;
    int w = blk >> 4;
    int cblk = blk & 15;
    const float* W = w ? Wo : Wq;
    int R = w ? 512 : 1536;
    int toff = w ? 1536 : 0;
    int dl = threadIdx.x & 31;
    int rg = threadIdx.x >> 5;
    int d = cblk * 32 + dl;
    float s = 0.f;
    for (int r = rg; r < R; r += 8) s += W[(size_t)r * 512 + d] * g_t[toff + r];
    __shared__ float red[8][33];
    red[rg][dl] = s;
    __syncthreads();
    if (rg == 0) {
        float cs = 0.f;
        #pragma unroll
        for (int q = 0; q < 8; ++q) cs += red[q][dl];
        cs = cs * cs;
        #pragma unroll
        for (int o = 16; o >= 1; o >>= 1) cs += __shfl_xor_sync(0xffffffffu, cs, o);
        if (dl == 0) g_part[blk] = cs;
    }
}

__global__ __launch_bounds__(256)
void sn_scale(const float* __restrict__ sq, const float* __restrict__ so)
{
    int w = blockIdx.x;
    int tid = threadIdx.x;
    float ssq = (tid < 16) ? g_part[w * 16 + tid] : 0.f;
    int R = w ? 512 : 1536;
    int off = w ? 1536 : 0;
    float tt = 0.f;
    for (int r = tid; r < R; r += 256) { float v = g_t[off + r]; tt += v * v; }
    __shared__ float ra[256], rb[256];
    ra[tid] = ssq; rb[tid] = tt;
    __syncthreads();
    for (int sft = 128; sft >= 1; sft >>= 1) {
        if (tid < sft) { ra[tid] += ra[tid + sft]; rb[tid] += rb[tid + sft]; }
        __syncthreads();
    }
    if (tid == 0) {
        float sigma_w = sqrtf(ra[0] / rb[0]);
        g_scales[w] = (w ? so[0] : sq[0]) / sigma_w;
    }
}

// ---------------------------------------------------------------------------
// tf32 GEMM: C[M,N] = (A[M,K] @ B[N,K]^T)*g_scales[si] (+bias)
// 128 threads (4 warps 2x2), CTA tile 128x128, warp tile 64x64, K-step 32,
// double-buffered smem, register prefetch, one sync per K-step.
// ---------------------------------------------------------------------------
__global__ __launch_bounds__(128)
void gemm_tf32(const float* __restrict__ A, const float* __restrict__ B,
               float* __restrict__ C, int M, int N, int K,
               int scale_idx, const float* __restrict__ bias)
{
    extern __shared__ unsigned smg[];
    unsigned* As = smg;                 // [2][128*36]
    unsigned* Bs = smg + 2 * 128 * 36;  // [2][128*36]
    const int t    = threadIdx.x;
    const int lane = t & 31;
    const int wid  = t >> 5;
    const int g  = lane >> 2;
    const int tg = lane & 3;
    const int wm = (wid >> 1) * 64;
    const int wn = (wid & 1) * 64;
    const int row0 = blockIdx.y * 128;
    const int col0 = blockIdx.x * 128;

    const int lr = t >> 3;          // 0..15
    const int lc4 = (t & 7) << 2;   // 0,4,..,28

    float4 pa[8], pb[8];
    #pragma unroll
    for (int i = 0; i < 8; ++i) {
        pa[i] = *(const float4*)&A[(size_t)(row0 + lr + i * 16) * K + lc4];
        pb[i] = *(const float4*)&B[(size_t)(col0 + lr + i * 16) * K + lc4];
    }
    #pragma unroll
    for (int i = 0; i < 8; ++i) {
        int r = lr + i * 16;
        uint4 ua = make_uint4(f2tf(pa[i].x), f2tf(pa[i].y), f2tf(pa[i].z), f2tf(pa[i].w));
        uint4 ub = make_uint4(f2tf(pb[i].x), f2tf(pb[i].y), f2tf(pb[i].z), f2tf(pb[i].w));
        *(uint4*)&As[r * 36 + lc4] = ua;
        *(uint4*)&Bs[r * 36 + lc4] = ub;
    }

    float acc[4][8][4];
    #pragma unroll
    for (int mi = 0; mi < 4; ++mi)
        #pragma unroll
        for (int ni = 0; ni < 8; ++ni)
            #pragma unroll
            for (int r = 0; r < 4; ++r) acc[mi][ni][r] = 0.f;

    int buf = 0;
    for (int k0 = 0; k0 < K; k0 += 32) {
        __syncthreads();
        const bool nxt = (k0 + 32) < K;
        if (nxt) {
            #pragma unroll
            for (int i = 0; i < 8; ++i) {
                pa[i] = *(const float4*)&A[(size_t)(row0 + lr + i * 16) * K + k0 + 32 + lc4];
                pb[i] = *(const float4*)&B[(size_t)(col0 + lr + i * 16) * K + k0 + 32 + lc4];
            }
        }
        const unsigned* Ab = As + buf * (128 * 36);
        const unsigned* Bb = Bs + buf * (128 * 36);
        #pragma unroll
        for (int ki = 0; ki < 4; ++ki) {
            const int kk = ki * 8;
            unsigned af[4][4], bf[8][2];
            #pragma unroll
            for (int mi = 0; mi < 4; ++mi) {
                int r = wm + mi * 16;
                af[mi][0] = Ab[(r + g) * 36 + kk + tg];
                af[mi][1] = Ab[(r + g + 8) * 36 + kk + tg];
                af[mi][2] = Ab[(r + g) * 36 + kk + tg + 4];
                af[mi][3] = Ab[(r + g + 8) * 36 + kk + tg + 4];
            }
            #pragma unroll
            for (int ni = 0; ni < 8; ++ni) {
                int c = wn + ni * 8;
                bf[ni][0] = Bb[(c + g) * 36 + kk + tg];
                bf[ni][1] = Bb[(c + g) * 36 + kk + tg + 4];
            }
            #pragma unroll
            for (int mi = 0; mi < 4; ++mi)
                #pragma unroll
                for (int ni = 0; ni < 8; ++ni)
                    mma8(acc[mi][ni], af[mi], bf[ni]);
        }
        if (nxt) {
            unsigned* An = As + (buf ^ 1) * (128 * 36);
            unsigned* Bn = Bs + (buf ^ 1) * (128 * 36);
            #pragma unroll
            for (int i = 0; i < 8; ++i) {
                int r = lr + i * 16;
                uint4 ua = make_uint4(f2tf(pa[i].x), f2tf(pa[i].y), f2tf(pa[i].z), f2tf(pa[i].w));
                uint4 ub = make_uint4(f2tf(pb[i].x), f2tf(pb[i].y), f2tf(pb[i].z), f2tf(pb[i].w));
                *(uint4*)&An[r * 36 + lc4] = ua;
                *(uint4*)&Bn[r * 36 + lc4] = ub;
            }
        }
        buf ^= 1;
    }

    const float scale = g_scales[scale_idx];
    #pragma unroll
    for (int mi = 0; mi < 4; ++mi) {
        int r = row0 + wm + mi * 16 + g;
        #pragma unroll
        for (int ni = 0; ni < 8; ++ni) {
            int c = col0 + wn + ni * 8 + tg * 2;
            float b0 = 0.f, b1 = 0.f;
            if (bias) { b0 = bias[c]; b1 = bias[c + 1]; }
            float2 lo, hi;
            lo.x = acc[mi][ni][0] * scale + b0;
            lo.y = acc[mi][ni][1] * scale + b1;
            hi.x = acc[mi][ni][2] * scale + b0;
            hi.y = acc[mi][ni][3] * scale + b1;
            *(float2*)&C[(size_t)r * N + c]       = lo;
            *(float2*)&C[(size_t)(r + 8) * N + c] = hi;
        }
    }
}

// ---------------------------------------------------------------------------
// Flash attention (no-max variant; logits are tiny by construction).
// 128 threads (4 warps). Bq=128 (warp w owns query cols w*32..+31), Bk=64.
// Computes S^T = K @ Q^T and O^T = V^T @ P^T so K/V fragments amortize over
// 32 query columns. Q fragments live in registers across the whole KV loop.
// Double-buffered K/V smem, one __syncthreads per KV tile.
// Grid (SEQ/128, B*H) = (16,16).
// ---------------------------------------------------------------------------
__global__ __launch_bounds__(128)
void attn_tf32(const float* __restrict__ qkv,
               const float* __restrict__ temp,
               float* __restrict__ out)
{
    extern __shared__ unsigned sm[];
    unsigned* Ks = sm;                          // [2][64][68]
    unsigned* Vs = sm + 2 * 64 * 68;            // [2][64][72]
    unsigned* Ps = sm + 2 * 64 * 68 + 2 * 64 * 72; // [64][136] P^T; Q staging [128][68]

    const int t    = threadIdx.x;
    const int lane = t & 31;
    const int w    = t >> 5;       // 0..3
    const int g    = lane >> 2;    // 0..7
    const int tg   = lane & 3;     // 0..3
    const int bh = blockIdx.y;
    const int b  = bh >> 3;
    const int h  = bh & 7;
    const int s0 = blockIdx.x * 128;
    const int wi0 = w * 32;        // this warp's query-column base (local)

    const float k2 = __expf(temp[0]) * 1.4426950408889634f;
    const float* base = qkv + (size_t)b * SEQ * QKV3 + h * DHEAD;

    const int lr  = t >> 4;          // 0..7
    const int lc4 = (t & 15) << 2;   // 0..60

    // prefetch K/V tile 0
    float4 pk[8], pv[8];
    #pragma unroll
    for (int i = 0; i < 8; ++i) {
        const float* rp = base + (size_t)(lr + i * 8) * QKV3 + lc4;
        pk[i] = *(const float4*)(rp + 512);
        pv[i] = *(const float4*)(rp + 1024);
    }

    // stage Q [128][64] (tf32) into Ps region, stride 68
    #pragma unroll
    for (int i = 0; i < 16; ++i) {
        int r = lr + i * 8;
        float4 v = *(const float4*)&base[(size_t)(s0 + r) * QKV3 + lc4];
        uint4 u = make_uint4(f2tf(v.x), f2tf(v.y), f2tf(v.z), f2tf(v.w));
        *(uint4*)&Ps[r * 68 + lc4] = u;
    }
    __syncthreads();

    // Q fragments (B-operand): qf[nb][ki][2], cached for the whole loop
    unsigned qf[4][8][2];
    #pragma unroll
    for (int nb = 0; nb < 4; ++nb)
        #pragma unroll
        for (int ki = 0; ki < 8; ++ki) {
            qf[nb][ki][0] = Ps[(wi0 + nb * 8 + g) * 68 + ki * 8 + tg];
            qf[nb][ki][1] = Ps[(wi0 + nb * 8 + g) * 68 + ki * 8 + tg + 4];
        }

    // store K/V tile 0 into stage 0
    #pragma unroll
    for (int i = 0; i < 8; ++i) {
        int r = lr + i * 8;
        uint4 uk = make_uint4(f2tf(pk[i].x), f2tf(pk[i].y), f2tf(pk[i].z), f2tf(pk[i].w));
        uint4 uv = make_uint4(f2tf(pv[i].x), f2tf(pv[i].y), f2tf(pv[i].z), f2tf(pv[i].w));
        *(uint4*)&Ks[r * 68 + lc4] = uk;
        *(uint4*)&Vs[r * 72 + lc4] = uv;
    }

    float o[4][4][4];     // [db][nb][frag]  O^T accumulators (d rows, i cols)
    #pragma unroll
    for (int db = 0; db < 4; ++db)
        #pragma unroll
        for (int nb = 0; nb < 4; ++nb)
            #pragma unroll
            for (int r = 0; r < 4; ++r) o[db][nb][r] = 0.f;
    float l[4][2];
    #pragma unroll
    for (int nb = 0; nb < 4; ++nb) { l[nb][0] = 0.f; l[nb][1] = 0.f; }

    int buf = 0;
    for (int kt = 0; kt < SEQ / 64; ++kt) {
        __syncthreads();
        const bool nxt = kt < (SEQ / 64 - 1);
        if (nxt) {
            const int j0n = (kt + 1) * 64;
            #pragma unroll
            for (int i = 0; i < 8; ++i) {
                const float* rp = base + (size_t)(j0n + lr + i * 8) * QKV3 + lc4;
                pk[i] = *(const float4*)(rp + 512);
                pv[i] = *(const float4*)(rp + 1024);
            }
        }
        const unsigned* Kb = Ks + buf * (64 * 68);
        const unsigned* Vb = Vs + buf * (64 * 72);
        const int j0 = kt * 64;

        // S^T = K @ Q^T, processed in two 32-row halves to bound registers
        #pragma unroll
        for (int mh = 0; mh < 2; ++mh) {
            float s[2][4][4];
            #pragma unroll
            for (int mb = 0; mb < 2; ++mb)
                #pragma unroll
                for (int nb = 0; nb < 4; ++nb)
                    #pragma unroll
                    for (int r = 0; r < 4; ++r) s[mb][nb][r] = 0.f;
            #pragma unroll
            for (int ki = 0; ki < 8; ++ki) {
                unsigned af[2][4];
                #pragma unroll
                for (int mb = 0; mb < 2; ++mb) {
                    int r = mh * 32 + mb * 16;
                    af[mb][0] = Kb[(r + g) * 68 + ki * 8 + tg];
                    af[mb][1] = Kb[(r + g + 8) * 68 + ki * 8 + tg];
                    af[mb][2] = Kb[(r + g) * 68 + ki * 8 + tg + 4];
                    af[mb][3] = Kb[(r + g + 8) * 68 + ki * 8 + tg + 4];
                }
                #pragma unroll
                for (int mb = 0; mb < 2; ++mb)
                    #pragma unroll
                    for (int nb = 0; nb < 4; ++nb)
                        mma8(s[mb][nb], af[mb], qf[nb][ki]);
            }
            // exp (no max shift) + mask + column-sum partials + store P^T
            #pragma unroll
            for (int mb = 0; mb < 2; ++mb) {
                const int jl = mh * 32 + mb * 16 + g;      // local j for frag rows
                const int jg = j0 + jl;                    // global key index
                #pragma unroll
                for (int nb = 0; nb < 4; ++nb) {
                    const int ig = s0 + wi0 + nb * 8 + tg * 2;  // global query index
                    float v0 = s[mb][nb][0] * k2;
                    float v1 = s[mb][nb][1] * k2;
                    float v2 = s[mb][nb][2] * k2;
                    float v3 = s[mb][nb][3] * k2;
                    if ((unsigned)(ig     - jg)       < 8u) v0 = -1e30f;
                    if ((unsigned)(ig + 1 - jg)       < 8u) v1 = -1e30f;
                    if ((unsigned)(ig     - (jg + 8)) < 8u) v2 = -1e30f;
                    if ((unsigned)(ig + 1 - (jg + 8)) < 8u) v3 = -1e30f;
                    float p0 = exp2c(v0);
                    float p1 = exp2c(v1);
                    float p2 = exp2c(v2);
                    float p3 = exp2c(v3);
                    l[nb][0] += p0 + p2;
                    l[nb][1] += p1 + p3;
                    const int ic = wi0 + nb * 8 + tg * 2;
                    uint2 u01 = make_uint2(f2tf(p0), f2tf(p1));
                    uint2 u23 = make_uint2(f2tf(p2), f2tf(p3));
                    *(uint2*)&Ps[jl * 136 + ic]       = u01;
                    *(uint2*)&Ps[(jl + 8) * 136 + ic] = u23;
                }
            }
        }
        __syncwarp();

        // O^T += V^T @ P^T
        #pragma unroll
        for (int kj = 0; kj < 8; ++kj) {
            unsigned pf[4][2];
            #pragma unroll
            for (int nb = 0; nb < 4; ++nb) {
                pf[nb][0] = Ps[(kj * 8 + tg) * 136 + wi0 + nb * 8 + g];
                pf[nb][1] = Ps[(kj * 8 + tg + 4) * 136 + wi0 + nb * 8 + g];
            }
            #pragma unroll
            for (int db = 0; db < 4; ++db) {
                unsigned vf[4];
                vf[0] = Vb[(kj * 8 + tg) * 72 + db * 16 + g];
                vf[1] = Vb[(kj * 8 + tg) * 72 + db * 16 + g + 8];
                vf[2] = Vb[(kj * 8 + tg + 4) * 72 + db * 16 + g];
                vf[3] = Vb[(kj * 8 + tg + 4) * 72 + db * 16 + g + 8];
                #pragma unroll
                for (int nb = 0; nb < 4; ++nb)
                    mma8(o[db][nb], vf, pf[nb]);
            }
        }

        if (nxt) {
            unsigned* Kn = Ks + (buf ^ 1) * (64 * 68);
            unsigned* Vn = Vs + (buf ^ 1) * (64 * 72);
            #pragma unroll
            for (int i = 0; i < 8; ++i) {
                int r = lr + i * 8;
                uint4 uk = make_uint4(f2tf(pk[i].x), f2tf(pk[i].y), f2tf(pk[i].z), f2tf(pk[i].w));
                uint4 uv = make_uint4(f2tf(pv[i].x), f2tf(pv[i].y), f2tf(pv[i].z), f2tf(pv[i].w));
                *(uint4*)&Kn[r * 68 + lc4] = uk;
                *(uint4*)&Vn[r * 72 + lc4] = uv;
            }
        }
        buf ^= 1;
    }

    // finish column sums (reduce over g lanes: xor 4, 8, 16)
    #pragma unroll
    for (int nb = 0; nb < 4; ++nb) {
        #pragma unroll
        for (int c = 0; c < 2; ++c) {
            float v = l[nb][c];
            v += __shfl_xor_sync(0xffffffffu, v, 4);
            v += __shfl_xor_sync(0xffffffffu, v, 8);
            v += __shfl_xor_sync(0xffffffffu, v, 16);
            l[nb][c] = v;
        }
    }

    // epilogue: out[b][s0+wi0+i][h*64+d] = O^T[d][i] / l[i]
    float* ob = out + ((size_t)b * SEQ + s0 + wi0) * INNER + h * DHEAD;
    #pragma unroll
    for (int nb = 0; nb < 4; ++nb) {
        const int i0 = nb * 8 + tg * 2;
        const float inv0 = 1.f / l[nb][0];
        const float inv1 = 1.f / l[nb][1];
        #pragma unroll
        for (int db = 0; db < 4; ++db) {
            const int d0 = db * 16 + g;
            ob[(size_t)i0 * INNER + d0]           = o[db][nb][0] * inv0;
            ob[(size_t)(i0 + 1) * INNER + d0]     = o[db][nb][1] * inv1;
            ob[(size_t)i0 * INNER + d0 + 8]       = o[db][nb][2] * inv0;
            ob[(size_t)(i0 + 1) * INNER + d0 + 8] = o[db][nb][3] * inv1;
        }
    }
}

// ---------------------------------------------------------------------------
extern "C" void kernel_launch(void* const* d_in, const int* in_sizes, int n_in,
                              void* d_out, int out_size)
{
    const float* x    = (const float*)d_in[0];
    const float* Wq   = (const float*)d_in[1];
    const float* uq   = (const float*)d_in[2];
    const float* sq   = (const float*)d_in[3];
    const float* Wo   = (const float*)d_in[4];
    const float* bo   = (const float*)d_in[5];
    const float* uo   = (const float*)d_in[6];
    const float* so   = (const float*)d_in[7];
    const float* temp = (const float*)d_in[8];

    float* p_qkv  = nullptr;
    float* p_attn = nullptr;
    cudaGetSymbolAddress((void**)&p_qkv,  g_qkv);
    cudaGetSymbolAddress((void**)&p_attn, g_attn);

    // spectral-norm scale factors
    sn_rowdot<<<2048, 128>>>(Wq, uq, Wo, uo);
    sn_coldot<<<32, 256>>>(Wq, Wo);
    sn_scale<<<2, 256>>>(sq, so);

    const int smem_gemm = 2 * 128 * 36 * 2 * (int)sizeof(unsigned);   // 73728
    cudaFuncSetAttribute(gemm_tf32, cudaFuncAttributeMaxDynamicSharedMemorySize, smem_gemm);

    // qkv = (x @ W_qkv^T) * scale_qkv
    gemm_tf32<<<dim3(QKV3 / 128, MROWS / 128), 128, smem_gemm>>>(
        x, Wq, p_qkv, MROWS, QKV3, DMODEL, 0, (const float*)nullptr);

    // attention
    const int smem_attn = (2 * 64 * 68 + 2 * 64 * 72 + 64 * 136) * (int)sizeof(unsigned); // 106496
    cudaFuncSetAttribute(attn_tf32, cudaFuncAttributeMaxDynamicSharedMemorySize, smem_attn);
    attn_tf32<<<dim3(SEQ / 128, BATCH * NHEADS), 128, smem_attn>>>(p_qkv, temp, p_attn);

    // out = (attn @ W_out^T) * scale_out + b_out
    gemm_tf32<<<dim3(DMODEL / 128, MROWS / 128), 128, smem_gemm>>>(
        p_attn, Wo, (float*)d_out, MROWS, DMODEL, INNER, 1, bo);
}

// round 5
// speedup vs baseline: 4.0602x; 1.1602x over previous
#include <cuda_runtime.h>
#include <math.h>

#define BATCH 2
#define SEQ   2048
#define DMODEL 512
#define NHEADS 8
#define DHEAD 64
#define INNER 512
#define QKV3  1536
#define MROWS (BATCH*SEQ)   // 4096

// Scratch (device globals; allocation is forbidden)
__device__ float g_qkv[BATCH * SEQ * QKV3];     // [b,s,1536] tf32-rounded
__device__ float g_attn[BATCH * SEQ * INNER];   // [b,s,512]
__device__ float g_t[2048];
__device__ float g_part[32];
__device__ float g_scales[2];

// ---------------------------------------------------------------------------
// helpers
// ---------------------------------------------------------------------------
__device__ __forceinline__ unsigned f2tf(float x) {
    unsigned r;
    asm("cvt.rna.tf32.f32 %0, %1;" : "=r"(r) : "f"(x));
    return r;
}

__device__ __forceinline__ float ex2f(float x) {
    float r;
    asm("ex2.approx.ftz.f32 %0, %1;" : "=f"(r) : "f"(x));
    return r;
}

__device__ __forceinline__ void mma8(float* c, const unsigned* a, const unsigned* b) {
    asm volatile(
        "mma.sync.aligned.m16n8k8.row.col.f32.tf32.tf32.f32 "
        "{%0,%1,%2,%3}, {%4,%5,%6,%7}, {%8,%9}, {%0,%1,%2,%3};"
        : "+f"(c[0]), "+f"(c[1]), "+f"(c[2]), "+f"(c[3])
        : "r"(a[0]), "r"(a[1]), "r"(a[2]), "r"(a[3]), "r"(b[0]), "r"(b[1]));
}

__device__ __forceinline__ void cpa16(unsigned dst, const float* src) {
    asm volatile("cp.async.cg.shared.global [%0], [%1], 16;" :: "r"(dst), "l"(src));
}
#define CP_COMMIT() asm volatile("cp.async.commit_group;")
#define CP_WAIT1()  asm volatile("cp.async.wait_group 1;")

// ---------------------------------------------------------------------------
// Spectral norm: sigma_w = ||W^T (Wu/||Wu||)||, scale = sigma_in / sigma_w
// ---------------------------------------------------------------------------
__global__ __launch_bounds__(128)
void sn_rowdot(const float* __restrict__ Wq, const float* __restrict__ uq,
               const float* __restrict__ Wo, const float* __restrict__ uo)
{
    int rb = blockIdx.x;
    const float* W; const float* u; int row;
    if (rb < 1536) { W = Wq; u = uq; row = rb; }
    else           { W = Wo; u = uo; row = rb - 1536; }
    const float* wr = W + (size_t)row * 512;
    float s = 0.f;
    for (int c = threadIdx.x; c < 512; c += 128) s += wr[c] * u[c];
    #pragma unroll
    for (int o = 16; o >= 1; o >>= 1) s += __shfl_xor_sync(0xffffffffu, s, o);
    __shared__ float red[4];
    if ((threadIdx.x & 31) == 0) red[threadIdx.x >> 5] = s;
    __syncthreads();
    if (threadIdx.x == 0) g_t[rb] = red[0] + red[1] + red[2] + red[3];
}

__global__ __launch_bounds__(256)
void sn_coldot(const float* __restrict__ Wq, const float* __restrict__ Wo)
{
    int blk = blockIdx.x;
    int w = blk >> 4;
    int cblk = blk & 15;
    const float* W = w ? Wo : Wq;
    int R = w ? 512 : 1536;
    int toff = w ? 1536 : 0;
    int dl = threadIdx.x & 31;
    int rg = threadIdx.x >> 5;
    int d = cblk * 32 + dl;
    float s = 0.f;
    for (int r = rg; r < R; r += 8) s += W[(size_t)r * 512 + d] * g_t[toff + r];
    __shared__ float red[8][33];
    red[rg][dl] = s;
    __syncthreads();
    if (rg == 0) {
        float cs = 0.f;
        #pragma unroll
        for (int q = 0; q < 8; ++q) cs += red[q][dl];
        cs = cs * cs;
        #pragma unroll
        for (int o = 16; o >= 1; o >>= 1) cs += __shfl_xor_sync(0xffffffffu, cs, o);
        if (dl == 0) g_part[blk] = cs;
    }
}

__global__ __launch_bounds__(256)
void sn_scale(const float* __restrict__ sq, const float* __restrict__ so)
{
    int w = blockIdx.x;
    int tid = threadIdx.x;
    float ssq = (tid < 16) ? g_part[w * 16 + tid] : 0.f;
    int R = w ? 512 : 1536;
    int off = w ? 1536 : 0;
    float tt = 0.f;
    for (int r = tid; r < R; r += 256) { float v = g_t[off + r]; tt += v * v; }
    __shared__ float ra[256], rb[256];
    ra[tid] = ssq; rb[tid] = tt;
    __syncthreads();
    for (int sft = 128; sft >= 1; sft >>= 1) {
        if (tid < sft) { ra[tid] += ra[tid + sft]; rb[tid] += rb[tid + sft]; }
        __syncthreads();
    }
    if (tid == 0) {
        float sigma_w = sqrtf(ra[0] / rb[0]);
        g_scales[w] = (w ? so[0] : sq[0]) / sigma_w;
    }
}

// ---------------------------------------------------------------------------
// tf32 GEMM: C[M,N] = (A[M,K] @ B[N,K]^T)*g_scales[si] (+bias)
// 128 thr / 4 warps (2x2), CTA 128x128, warp 64x64, K-step 32,
// 3-stage cp.async pipeline, cvt.rna on fragment read, 2 CTAs/SM.
// ---------------------------------------------------------------------------
#define GST (128 * 36)          // one operand stage in words
__global__ __launch_bounds__(128, 2)
void gemm_tf32(const float* __restrict__ A, const float* __restrict__ B,
               float* __restrict__ C, int M, int N, int K,
               int scale_idx, const float* __restrict__ bias, int round_out)
{
    extern __shared__ float smg[];        // [3][2*GST]
    const int t    = threadIdx.x;
    const int lane = t & 31;
    const int wid  = t >> 5;
    const int g  = lane >> 2;
    const int tg = lane & 3;
    const int wm = (wid >> 1) * 64;
    const int wn = (wid & 1) * 64;
    const int row0 = blockIdx.y * 128;
    const int col0 = blockIdx.x * 128;
    const int NK = K >> 5;

    const unsigned sb = (unsigned)__cvta_generic_to_shared(smg);
    const int crow = t >> 3;              // 0..15 (x8 rows)
    const int cch  = (t & 7) << 2;        // word offset 0..28

    // issue one stage (A tile 128x32 + B tile 128x32, raw fp32)
    auto issue = [&](int st, int k0) {
        unsigned so = sb + (unsigned)(st * 2 * GST) * 4u;
        #pragma unroll
        for (int i = 0; i < 8; ++i) {
            int row = crow + i * 16;
            cpa16(so + (unsigned)(row * 36 + cch) * 4u,
                  &A[(size_t)(row0 + row) * K + k0 + cch]);
            cpa16(so + (unsigned)(GST + row * 36 + cch) * 4u,
                  &B[(size_t)(col0 + row) * K + k0 + cch]);
        }
    };

    issue(0, 0);  CP_COMMIT();
    issue(1, 32); CP_COMMIT();

    float acc[4][8][4];
    #pragma unroll
    for (int mi = 0; mi < 4; ++mi)
        #pragma unroll
        for (int ni = 0; ni < 8; ++ni)
            #pragma unroll
            for (int r = 0; r < 4; ++r) acc[mi][ni][r] = 0.f;

    for (int ks = 0; ks < NK; ++ks) {
        CP_WAIT1();            // stage ks complete
        __syncthreads();       // visible to all; stage (ks+2)%3 free
        if (ks + 2 < NK) issue((ks + 2) % 3, (ks + 2) * 32);
        CP_COMMIT();

        const float* Ab = smg + (ks % 3) * 2 * GST;
        const float* Bb = Ab + GST;
        #pragma unroll
        for (int ki = 0; ki < 4; ++ki) {
            const int kk = ki * 8;
            unsigned af[4][4], bf[8][2];
            #pragma unroll
            for (int mi = 0; mi < 4; ++mi) {
                int r = wm + mi * 16;
                af[mi][0] = f2tf(Ab[(r + g) * 36 + kk + tg]);
                af[mi][1] = f2tf(Ab[(r + g + 8) * 36 + kk + tg]);
                af[mi][2] = f2tf(Ab[(r + g) * 36 + kk + tg + 4]);
                af[mi][3] = f2tf(Ab[(r + g + 8) * 36 + kk + tg + 4]);
            }
            #pragma unroll
            for (int ni = 0; ni < 8; ++ni) {
                int c = wn + ni * 8;
                bf[ni][0] = f2tf(Bb[(c + g) * 36 + kk + tg]);
                bf[ni][1] = f2tf(Bb[(c + g) * 36 + kk + tg + 4]);
            }
            #pragma unroll
            for (int mi = 0; mi < 4; ++mi)
                #pragma unroll
                for (int ni = 0; ni < 8; ++ni)
                    mma8(acc[mi][ni], af[mi], bf[ni]);
        }
    }

    const float scale = g_scales[scale_idx];
    #pragma unroll
    for (int mi = 0; mi < 4; ++mi) {
        int r = row0 + wm + mi * 16 + g;
        #pragma unroll
        for (int ni = 0; ni < 8; ++ni) {
            int c = col0 + wn + ni * 8 + tg * 2;
            float b0 = 0.f, b1 = 0.f;
            if (bias) { b0 = bias[c]; b1 = bias[c + 1]; }
            float v0 = acc[mi][ni][0] * scale + b0;
            float v1 = acc[mi][ni][1] * scale + b1;
            float v2 = acc[mi][ni][2] * scale + b0;
            float v3 = acc[mi][ni][3] * scale + b1;
            if (round_out) {
                v0 = __uint_as_float(f2tf(v0));
                v1 = __uint_as_float(f2tf(v1));
                v2 = __uint_as_float(f2tf(v2));
                v3 = __uint_as_float(f2tf(v3));
            }
            *(float2*)&C[(size_t)r * N + c]       = make_float2(v0, v1);
            *(float2*)&C[(size_t)(r + 8) * N + c] = make_float2(v2, v3);
        }
    }
}

// ---------------------------------------------------------------------------
// Flash attention (no-max; logits bounded). qkv is tf32-pre-rounded in gmem.
// 128 thr / 4 warps, Bq=128 (warp w owns query cols w*32..+31), Bk=64.
// S^T = K @ Q^T, O^T = V^T @ P^T. Q pre-scaled by exp(T)*log2e at staging.
// 2-stage cp.async K/V pipeline, MUFU ex2 softmax, 2 CTAs/SM.
// ---------------------------------------------------------------------------
#define KOFF(buf) ((buf) * (64 * 68))
#define VOFF(buf) (2 * 64 * 68 + (buf) * (64 * 72))
#define POFF      (2 * 64 * 68 + 2 * 64 * 72)

__global__ __launch_bounds__(128, 2)
void attn_tf32(const float* __restrict__ qkv,
               const float* __restrict__ temp,
               float* __restrict__ out)
{
    extern __shared__ float sma[];        // K[2][64*68] V[2][64*72] P/Q[64*136]
    const int t    = threadIdx.x;
    const int lane = t & 31;
    const int w    = t >> 5;
    const int g    = lane >> 2;
    const int tg   = lane & 3;
    const int bh = blockIdx.y;
    const int b  = bh >> 3;
    const int h  = bh & 7;
    const int s0 = blockIdx.x * 128;
    const int wi0 = w * 32;

    const float k2 = __expf(temp[0]) * 1.4426950408889634f;
    const float* base = qkv + (size_t)b * SEQ * QKV3 + h * DHEAD;

    const unsigned sb = (unsigned)__cvta_generic_to_shared(sma);
    const int lr  = t >> 4;          // 0..7
    const int lc4 = (t & 15) << 2;   // 0..60

    // issue K/V tile via cp.async (raw bits: already tf32-rounded)
    auto issueKV = [&](int buf, int j0) {
        #pragma unroll
        for (int i = 0; i < 8; ++i) {
            int row = lr + i * 8;
            const float* rp = base + (size_t)(j0 + row) * QKV3 + lc4;
            cpa16(sb + (unsigned)(KOFF(buf) + row * 68 + lc4) * 4u, rp + 512);
            cpa16(sb + (unsigned)(VOFF(buf) + row * 72 + lc4) * 4u, rp + 1024);
        }
    };

    issueKV(0, 0); CP_COMMIT();

    // stage Q [128][64] into P region (stride 68), pre-scaled by k2
    float* Psf = sma + POFF;
    unsigned* Psu = (unsigned*)Psf;
    #pragma unroll
    for (int i = 0; i < 16; ++i) {
        int r = lr + i * 8;
        float4 v = *(const float4*)&base[(size_t)(s0 + r) * QKV3 + lc4];
        unsigned* p = &Psu[r * 68 + lc4];
        p[0] = f2tf(v.x * k2); p[1] = f2tf(v.y * k2);
        p[2] = f2tf(v.z * k2); p[3] = f2tf(v.w * k2);
    }
    __syncthreads();

    // Q fragments cached in registers for the whole KV loop
    unsigned qf[4][8][2];
    #pragma unroll
    for (int nb = 0; nb < 4; ++nb)
        #pragma unroll
        for (int ki = 0; ki < 8; ++ki) {
            qf[nb][ki][0] = Psu[(wi0 + nb * 8 + g) * 68 + ki * 8 + tg];
            qf[nb][ki][1] = Psu[(wi0 + nb * 8 + g) * 68 + ki * 8 + tg + 4];
        }

    float o[4][4][4];
    #pragma unroll
    for (int db = 0; db < 4; ++db)
        #pragma unroll
        for (int nb = 0; nb < 4; ++nb)
            #pragma unroll
            for (int r = 0; r < 4; ++r) o[db][nb][r] = 0.f;
    float l[4][2];
    #pragma unroll
    for (int nb = 0; nb < 4; ++nb) { l[nb][0] = 0.f; l[nb][1] = 0.f; }

    int buf = 0;
    for (int kt = 0; kt < SEQ / 64; ++kt) {
        __syncthreads();                      // all warps done with buf^1
        if (kt + 1 < SEQ / 64) issueKV(buf ^ 1, (kt + 1) * 64);
        CP_COMMIT();
        CP_WAIT1();                           // tile kt arrived
        __syncthreads();                      // visible to all warps

        const unsigned* Kb = (const unsigned*)sma + KOFF(buf);
        const unsigned* Vb = (const unsigned*)sma + VOFF(buf);
        const int j0 = kt * 64;
        // warp's i in [s0+wi0, +31], j in [j0, +63]; band 0<=i-j<=7 intersects
        // iff -31 <= (s0+wi0-j0) <= 70  <=>  (unsigned)(d+31) <= 101
        const bool need_mask = (unsigned)(s0 + wi0 - j0 + 31) <= 101u;

        // S^T = K @ Q^T in two 32-row halves; softmax fused
        #pragma unroll
        for (int mh = 0; mh < 2; ++mh) {
            float s[2][4][4];
            #pragma unroll
            for (int mb = 0; mb < 2; ++mb)
                #pragma unroll
                for (int nb = 0; nb < 4; ++nb)
                    #pragma unroll
                    for (int r = 0; r < 4; ++r) s[mb][nb][r] = 0.f;
            #pragma unroll
            for (int ki = 0; ki < 8; ++ki) {
                unsigned af[2][4];
                #pragma unroll
                for (int mb = 0; mb < 2; ++mb) {
                    int r = mh * 32 + mb * 16;
                    af[mb][0] = Kb[(r + g) * 68 + ki * 8 + tg];
                    af[mb][1] = Kb[(r + g + 8) * 68 + ki * 8 + tg];
                    af[mb][2] = Kb[(r + g) * 68 + ki * 8 + tg + 4];
                    af[mb][3] = Kb[(r + g + 8) * 68 + ki * 8 + tg + 4];
                }
                #pragma unroll
                for (int mb = 0; mb < 2; ++mb)
                    #pragma unroll
                    for (int nb = 0; nb < 4; ++nb)
                        mma8(s[mb][nb], af[mb], qf[nb][ki]);
            }
            #pragma unroll
            for (int mb = 0; mb < 2; ++mb) {
                const int jl = mh * 32 + mb * 16 + g;
                const int jg = j0 + jl;
                #pragma unroll
                for (int nb = 0; nb < 4; ++nb) {
                    float v0 = s[mb][nb][0];
                    float v1 = s[mb][nb][1];
                    float v2 = s[mb][nb][2];
                    float v3 = s[mb][nb][3];
                    if (need_mask) {
                        const int ig = s0 + wi0 + nb * 8 + tg * 2;
                        if ((unsigned)(ig     - jg)       < 8u) v0 = -1e30f;
                        if ((unsigned)(ig + 1 - jg)       < 8u) v1 = -1e30f;
                        if ((unsigned)(ig     - (jg + 8)) < 8u) v2 = -1e30f;
                        if ((unsigned)(ig + 1 - (jg + 8)) < 8u) v3 = -1e30f;
                    }
                    float p0 = ex2f(v0);
                    float p1 = ex2f(v1);
                    float p2 = ex2f(v2);
                    float p3 = ex2f(v3);
                    l[nb][0] += p0 + p2;
                    l[nb][1] += p1 + p3;
                    const int ic = wi0 + nb * 8 + tg * 2;
                    *(uint2*)&Psu[jl * 136 + ic]       = make_uint2(f2tf(p0), f2tf(p1));
                    *(uint2*)&Psu[(jl + 8) * 136 + ic] = make_uint2(f2tf(p2), f2tf(p3));
                }
            }
        }
        __syncwarp();   // Ps stripe produced & consumed within the same warp

        // O^T += V^T @ P^T
        #pragma unroll
        for (int kj = 0; kj < 8; ++kj) {
            unsigned pf[4][2];
            #pragma unroll
            for (int nb = 0; nb < 4; ++nb) {
                pf[nb][0] = Psu[(kj * 8 + tg) * 136 + wi0 + nb * 8 + g];
                pf[nb][1] = Psu[(kj * 8 + tg + 4) * 136 + wi0 + nb * 8 + g];
            }
            #pragma unroll
            for (int db = 0; db < 4; ++db) {
                unsigned vf[4];
                vf[0] = Vb[(kj * 8 + tg) * 72 + db * 16 + g];
                vf[1] = Vb[(kj * 8 + tg) * 72 + db * 16 + g + 8];
                vf[2] = Vb[(kj * 8 + tg + 4) * 72 + db * 16 + g];
                vf[3] = Vb[(kj * 8 + tg + 4) * 72 + db * 16 + g + 8];
                #pragma unroll
                for (int nb = 0; nb < 4; ++nb)
                    mma8(o[db][nb], vf, pf[nb]);
            }
        }
        buf ^= 1;
    }

    // finish column sums (reduce over g lanes)
    #pragma unroll
    for (int nb = 0; nb < 4; ++nb) {
        #pragma unroll
        for (int c = 0; c < 2; ++c) {
            float v = l[nb][c];
            v += __shfl_xor_sync(0xffffffffu, v, 4);
            v += __shfl_xor_sync(0xffffffffu, v, 8);
            v += __shfl_xor_sync(0xffffffffu, v, 16);
            l[nb][c] = v;
        }
    }

    // epilogue: out[b][s0+wi0+i][h*64+d] = O^T[d][i] / l[i]
    float* ob = out + ((size_t)b * SEQ + s0 + wi0) * INNER + h * DHEAD;
    #pragma unroll
    for (int nb = 0; nb < 4; ++nb) {
        const int i0 = nb * 8 + tg * 2;
        const float inv0 = 1.f / l[nb][0];
        const float inv1 = 1.f / l[nb][1];
        #pragma unroll
        for (int db = 0; db < 4; ++db) {
            const int d0 = db * 16 + g;
            ob[(size_t)i0 * INNER + d0]           = o[db][nb][0] * inv0;
            ob[(size_t)(i0 + 1) * INNER + d0]     = o[db][nb][1] * inv1;
            ob[(size_t)i0 * INNER + d0 + 8]       = o[db][nb][2] * inv0;
            ob[(size_t)(i0 + 1) * INNER + d0 + 8] = o[db][nb][3] * inv1;
        }
    }
}

// ---------------------------------------------------------------------------
extern "C" void kernel_launch(void* const* d_in, const int* in_sizes, int n_in,
                              void* d_out, int out_size)
{
    const float* x    = (const float*)d_in[0];
    const float* Wq   = (const float*)d_in[1];
    const float* uq   = (const float*)d_in[2];
    const float* sq   = (const float*)d_in[3];
    const float* Wo   = (const float*)d_in[4];
    const float* bo   = (const float*)d_in[5];
    const float* uo   = (const float*)d_in[6];
    const float* so   = (const float*)d_in[7];
    const float* temp = (const float*)d_in[8];

    float* p_qkv  = nullptr;
    float* p_attn = nullptr;
    cudaGetSymbolAddress((void**)&p_qkv,  g_qkv);
    cudaGetSymbolAddress((void**)&p_attn, g_attn);

    // spectral-norm scale factors
    sn_rowdot<<<2048, 128>>>(Wq, uq, Wo, uo);
    sn_coldot<<<32, 256>>>(Wq, Wo);
    sn_scale<<<2, 256>>>(sq, so);

    const int smem_gemm = 3 * 2 * GST * (int)sizeof(float);   // 110592
    cudaFuncSetAttribute(gemm_tf32, cudaFuncAttributeMaxDynamicSharedMemorySize, smem_gemm);

    // qkv = (x @ W_qkv^T) * scale_qkv   (tf32-rounded output)
    gemm_tf32<<<dim3(QKV3 / 128, MROWS / 128), 128, smem_gemm>>>(
        x, Wq, p_qkv, MROWS, QKV3, DMODEL, 0, (const float*)nullptr, 1);

    // attention
    const int smem_attn = (2 * 64 * 68 + 2 * 64 * 72 + 64 * 136) * (int)sizeof(float); // 106496
    cudaFuncSetAttribute(attn_tf32, cudaFuncAttributeMaxDynamicSharedMemorySize, smem_attn);
    attn_tf32<<<dim3(SEQ / 128, BATCH * NHEADS), 128, smem_attn>>>(p_qkv, temp, p_attn);

    // out = (attn @ W_out^T) * scale_out + b_out
    gemm_tf32<<<dim3(DMODEL / 128, MROWS / 128), 128, smem_gemm>>>(
        p_attn, Wo, (float*)d_out, MROWS, DMODEL, INNER, 1, bo, 0);
}

// round 6
// speedup vs baseline: 4.1007x; 1.0100x over previous
#include <cuda_runtime.h>
#include <math.h>

#define BATCH 2
#define SEQ   2048
#define DMODEL 512
#define NHEADS 8
#define DHEAD 64
#define INNER 512
#define QKV3  1536
#define MROWS (BATCH*SEQ)   // 4096

// Scratch (device globals; allocation is forbidden)
__device__ float g_qkv[BATCH * SEQ * QKV3];     // [b,s,1536] tf32-rounded
__device__ float g_attn[BATCH * SEQ * INNER];   // [b,s,512]  tf32-rounded
__device__ float g_xr[MROWS * DMODEL];          // x, tf32-rounded
__device__ float g_wq[QKV3 * DMODEL];           // W_qkv, tf32-rounded
__device__ float g_wo[DMODEL * INNER];          // W_out, tf32-rounded
__device__ float g_t[2048];
__device__ float g_part[32];
__device__ float g_scales[2];

// ---------------------------------------------------------------------------
// helpers
// ---------------------------------------------------------------------------
__device__ __forceinline__ unsigned f2tf(float x) {
    unsigned r;
    asm("cvt.rna.tf32.f32 %0, %1;" : "=r"(r) : "f"(x));
    return r;
}

__device__ __forceinline__ float ex2f(float x) {
    float r;
    asm("ex2.approx.ftz.f32 %0, %1;" : "=f"(r) : "f"(x));
    return r;
}

__device__ __forceinline__ void mma8(float* c, const unsigned* a, const unsigned* b) {
    asm volatile(
        "mma.sync.aligned.m16n8k8.row.col.f32.tf32.tf32.f32 "
        "{%0,%1,%2,%3}, {%4,%5,%6,%7}, {%8,%9}, {%0,%1,%2,%3};"
        : "+f"(c[0]), "+f"(c[1]), "+f"(c[2]), "+f"(c[3])
        : "r"(a[0]), "r"(a[1]), "r"(a[2]), "r"(a[3]), "r"(b[0]), "r"(b[1]));
}

__device__ __forceinline__ void cpa16(unsigned dst, const float* src) {
    asm volatile("cp.async.cg.shared.global [%0], [%1], 16;" :: "r"(dst), "l"(src));
}
#define CP_COMMIT() asm volatile("cp.async.commit_group;")
#define CP_WAIT1()  asm volatile("cp.async.wait_group 1;")

// ---------------------------------------------------------------------------
// pre-round x / W_qkv / W_out to tf32 (removes all CVT from GEMM hot loops)
// ---------------------------------------------------------------------------
#define RN0 (MROWS * DMODEL / 4)
#define RN1 (QKV3 * DMODEL / 4)
#define RN2 (DMODEL * INNER / 4)
__global__ __launch_bounds__(256)
void round3(const float* __restrict__ x, const float* __restrict__ wq,
            const float* __restrict__ wo)
{
    int i = blockIdx.x * 256 + threadIdx.x;
    const float* src; float* dst; int off;
    if (i < RN0)            { src = x;  dst = g_xr; off = i; }
    else if (i < RN0 + RN1) { src = wq; dst = g_wq; off = i - RN0; }
    else                    { src = wo; dst = g_wo; off = i - RN0 - RN1; }
    float4 v = *(const float4*)(src + (size_t)off * 4);
    uint4 u = make_uint4(f2tf(v.x), f2tf(v.y), f2tf(v.z), f2tf(v.w));
    *(uint4*)(dst + (size_t)off * 4) = u;
}

// ---------------------------------------------------------------------------
// Spectral norm: sigma_w = ||W^T (Wu/||Wu||)||, scale = sigma_in / sigma_w
// (reads original full-precision weights, matching the reference)
// ---------------------------------------------------------------------------
__global__ __launch_bounds__(128)
void sn_rowdot(const float* __restrict__ Wq, const float* __restrict__ uq,
               const float* __restrict__ Wo, const float* __restrict__ uo)
{
    int rb = blockIdx.x;
    const float* W; const float* u; int row;
    if (rb < 1536) { W = Wq; u = uq; row = rb; }
    else           { W = Wo; u = uo; row = rb - 1536; }
    const float* wr = W + (size_t)row * 512;
    float s = 0.f;
    for (int c = threadIdx.x; c < 512; c += 128) s += wr[c] * u[c];
    #pragma unroll
    for (int o = 16; o >= 1; o >>= 1) s += __shfl_xor_sync(0xffffffffu, s, o);
    __shared__ float red[4];
    if ((threadIdx.x & 31) == 0) red[threadIdx.x >> 5] = s;
    __syncthreads();
    if (threadIdx.x == 0) g_t[rb] = red[0] + red[1] + red[2] + red[3];
}

__global__ __launch_bounds__(256)
void sn_coldot(const float* __restrict__ Wq, const float* __restrict__ Wo)
{
    int blk = blockIdx.x;
    int w = blk >> 4;
    int cblk = blk & 15;
    const float* W = w ? Wo : Wq;
    int R = w ? 512 : 1536;
    int toff = w ? 1536 : 0;
    int dl = threadIdx.x & 31;
    int rg = threadIdx.x >> 5;
    int d = cblk * 32 + dl;
    float s = 0.f;
    for (int r = rg; r < R; r += 8) s += W[(size_t)r * 512 + d] * g_t[toff + r];
    __shared__ float red[8][33];
    red[rg][dl] = s;
    __syncthreads();
    if (rg == 0) {
        float cs = 0.f;
        #pragma unroll
        for (int q = 0; q < 8; ++q) cs += red[q][dl];
        cs = cs * cs;
        #pragma unroll
        for (int o = 16; o >= 1; o >>= 1) cs += __shfl_xor_sync(0xffffffffu, cs, o);
        if (dl == 0) g_part[blk] = cs;
    }
}

__global__ __launch_bounds__(256)
void sn_scale(const float* __restrict__ sq, const float* __restrict__ so)
{
    int w = blockIdx.x;
    int tid = threadIdx.x;
    float ssq = (tid < 16) ? g_part[w * 16 + tid] : 0.f;
    int R = w ? 512 : 1536;
    int off = w ? 1536 : 0;
    float tt = 0.f;
    for (int r = tid; r < R; r += 256) { float v = g_t[off + r]; tt += v * v; }
    __shared__ float ra[256], rb[256];
    ra[tid] = ssq; rb[tid] = tt;
    __syncthreads();
    for (int sft = 128; sft >= 1; sft >>= 1) {
        if (tid < sft) { ra[tid] += ra[tid + sft]; rb[tid] += rb[tid + sft]; }
        __syncthreads();
    }
    if (tid == 0) {
        float sigma_w = sqrtf(ra[0] / rb[0]);
        g_scales[w] = (w ? so[0] : sq[0]) / sigma_w;
    }
}

// ---------------------------------------------------------------------------
// tf32 GEMM: C[M,N] = (A[M,K] @ B[N,K]^T)*g_scales[si] (+bias)
// A,B pre-rounded tf32. 256 thr / 8 warps (2x4), CTA 128x128, warp 64x32,
// K-step 32, 3-stage cp.async pipeline, NO cvt in hot loop, 2 CTAs/SM.
// ---------------------------------------------------------------------------
#define GST (128 * 36)          // one operand stage in words
__global__ __launch_bounds__(256, 2)
void gemm_tf32(const float* __restrict__ A, const float* __restrict__ B,
               float* __restrict__ C, int M, int N, int K,
               int scale_idx, const float* __restrict__ bias, int round_out)
{
    extern __shared__ float smg[];        // [3][2*GST]
    const int t    = threadIdx.x;
    const int lane = t & 31;
    const int wid  = t >> 5;              // 0..7
    const int g  = lane >> 2;
    const int tg = lane & 3;
    const int wm = (wid >> 2) * 64;       // 0 / 64
    const int wn = (wid & 3) * 32;        // 0/32/64/96
    const int row0 = blockIdx.y * 128;
    const int col0 = blockIdx.x * 128;
    const int NK = K >> 5;

    const unsigned sb = (unsigned)__cvta_generic_to_shared(smg);
    const int crow = t >> 3;              // 0..31 (x4 row groups)
    const int cch  = (t & 7) << 2;        // word offset 0..28

    auto issue = [&](int st, int k0) {
        unsigned so = sb + (unsigned)(st * 2 * GST) * 4u;
        #pragma unroll
        for (int i = 0; i < 4; ++i) {
            int row = crow + i * 32;
            cpa16(so + (unsigned)(row * 36 + cch) * 4u,
                  &A[(size_t)(row0 + row) * K + k0 + cch]);
            cpa16(so + (unsigned)(GST + row * 36 + cch) * 4u,
                  &B[(size_t)(col0 + row) * K + k0 + cch]);
        }
    };

    issue(0, 0);  CP_COMMIT();
    issue(1, 32); CP_COMMIT();

    float acc[4][4][4];
    #pragma unroll
    for (int mi = 0; mi < 4; ++mi)
        #pragma unroll
        for (int ni = 0; ni < 4; ++ni)
            #pragma unroll
            for (int r = 0; r < 4; ++r) acc[mi][ni][r] = 0.f;

    for (int ks = 0; ks < NK; ++ks) {
        CP_WAIT1();
        __syncthreads();
        if (ks + 2 < NK) issue((ks + 2) % 3, (ks + 2) * 32);
        CP_COMMIT();

        const unsigned* Ab = (const unsigned*)smg + (ks % 3) * 2 * GST;
        const unsigned* Bb = Ab + GST;
        #pragma unroll
        for (int ki = 0; ki < 4; ++ki) {
            const int kk = ki * 8;
            unsigned af[4][4], bf[4][2];
            #pragma unroll
            for (int mi = 0; mi < 4; ++mi) {
                int r = wm + mi * 16;
                af[mi][0] = Ab[(r + g) * 36 + kk + tg];
                af[mi][1] = Ab[(r + g + 8) * 36 + kk + tg];
                af[mi][2] = Ab[(r + g) * 36 + kk + tg + 4];
                af[mi][3] = Ab[(r + g + 8) * 36 + kk + tg + 4];
            }
            #pragma unroll
            for (int ni = 0; ni < 4; ++ni) {
                int c = wn + ni * 8;
                bf[ni][0] = Bb[(c + g) * 36 + kk + tg];
                bf[ni][1] = Bb[(c + g) * 36 + kk + tg + 4];
            }
            #pragma unroll
            for (int mi = 0; mi < 4; ++mi)
                #pragma unroll
                for (int ni = 0; ni < 4; ++ni)
                    mma8(acc[mi][ni], af[mi], bf[ni]);
        }
    }

    const float scale = g_scales[scale_idx];
    #pragma unroll
    for (int mi = 0; mi < 4; ++mi) {
        int r = row0 + wm + mi * 16 + g;
        #pragma unroll
        for (int ni = 0; ni < 4; ++ni) {
            int c = col0 + wn + ni * 8 + tg * 2;
            float b0 = 0.f, b1 = 0.f;
            if (bias) { b0 = bias[c]; b1 = bias[c + 1]; }
            float v0 = acc[mi][ni][0] * scale + b0;
            float v1 = acc[mi][ni][1] * scale + b1;
            float v2 = acc[mi][ni][2] * scale + b0;
            float v3 = acc[mi][ni][3] * scale + b1;
            if (round_out) {
                v0 = __uint_as_float(f2tf(v0));
                v1 = __uint_as_float(f2tf(v1));
                v2 = __uint_as_float(f2tf(v2));
                v3 = __uint_as_float(f2tf(v3));
            }
            *(float2*)&C[(size_t)r * N + c]       = make_float2(v0, v1);
            *(float2*)&C[(size_t)(r + 8) * N + c] = make_float2(v2, v3);
        }
    }
}

// ---------------------------------------------------------------------------
// Flash attention (no-max; logits bounded). qkv is tf32-pre-rounded in gmem.
// 128 thr / 4 warps, Bq=128 (warp w owns query cols w*32..+31), Bk=64.
// S^T = K @ Q^T, O^T = V^T @ P^T. Q pre-scaled by exp(T)*log2e at staging.
// 2-stage cp.async K/V pipeline, MUFU ex2 softmax, 2 CTAs/SM.
// Output stored tf32-rounded so the out-proj GEMM is cvt-free.
// ---------------------------------------------------------------------------
#define KOFF(buf) ((buf) * (64 * 68))
#define VOFF(buf) (2 * 64 * 68 + (buf) * (64 * 72))
#define POFF      (2 * 64 * 68 + 2 * 64 * 72)

__global__ __launch_bounds__(128, 2)
void attn_tf32(const float* __restrict__ qkv,
               const float* __restrict__ temp,
               float* __restrict__ out)
{
    extern __shared__ float sma[];        // K[2][64*68] V[2][64*72] P/Q[64*136]
    const int t    = threadIdx.x;
    const int lane = t & 31;
    const int w    = t >> 5;
    const int g    = lane >> 2;
    const int tg   = lane & 3;
    const int bh = blockIdx.y;
    const int b  = bh >> 3;
    const int h  = bh & 7;
    const int s0 = blockIdx.x * 128;
    const int wi0 = w * 32;

    const float k2 = __expf(temp[0]) * 1.4426950408889634f;
    const float* base = qkv + (size_t)b * SEQ * QKV3 + h * DHEAD;

    const unsigned sb = (unsigned)__cvta_generic_to_shared(sma);
    const int lr  = t >> 4;          // 0..7
    const int lc4 = (t & 15) << 2;   // 0..60

    auto issueKV = [&](int buf, int j0) {
        #pragma unroll
        for (int i = 0; i < 8; ++i) {
            int row = lr + i * 8;
            const float* rp = base + (size_t)(j0 + row) * QKV3 + lc4;
            cpa16(sb + (unsigned)(KOFF(buf) + row * 68 + lc4) * 4u, rp + 512);
            cpa16(sb + (unsigned)(VOFF(buf) + row * 72 + lc4) * 4u, rp + 1024);
        }
    };

    issueKV(0, 0); CP_COMMIT();

    // stage Q [128][64] into P region (stride 68), pre-scaled by k2
    unsigned* Psu = (unsigned*)(sma + POFF);
    #pragma unroll
    for (int i = 0; i < 16; ++i) {
        int r = lr + i * 8;
        float4 v = *(const float4*)&base[(size_t)(s0 + r) * QKV3 + lc4];
        unsigned* p = &Psu[r * 68 + lc4];
        p[0] = f2tf(v.x * k2); p[1] = f2tf(v.y * k2);
        p[2] = f2tf(v.z * k2); p[3] = f2tf(v.w * k2);
    }
    __syncthreads();

    unsigned qf[4][8][2];
    #pragma unroll
    for (int nb = 0; nb < 4; ++nb)
        #pragma unroll
        for (int ki = 0; ki < 8; ++ki) {
            qf[nb][ki][0] = Psu[(wi0 + nb * 8 + g) * 68 + ki * 8 + tg];
            qf[nb][ki][1] = Psu[(wi0 + nb * 8 + g) * 68 + ki * 8 + tg + 4];
        }

    float o[4][4][4];
    #pragma unroll
    for (int db = 0; db < 4; ++db)
        #pragma unroll
        for (int nb = 0; nb < 4; ++nb)
            #pragma unroll
            for (int r = 0; r < 4; ++r) o[db][nb][r] = 0.f;
    float l[4][2];
    #pragma unroll
    for (int nb = 0; nb < 4; ++nb) { l[nb][0] = 0.f; l[nb][1] = 0.f; }

    int buf = 0;
    for (int kt = 0; kt < SEQ / 64; ++kt) {
        __syncthreads();
        if (kt + 1 < SEQ / 64) issueKV(buf ^ 1, (kt + 1) * 64);
        CP_COMMIT();
        CP_WAIT1();
        __syncthreads();

        const unsigned* Kb = (const unsigned*)sma + KOFF(buf);
        const unsigned* Vb = (const unsigned*)sma + VOFF(buf);
        const int j0 = kt * 64;
        // warp's i in [s0+wi0, +31], j in [j0, +63]; band 0<=i-j<=7 intersects
        // iff -31 <= (s0+wi0-j0) <= 70  <=>  (unsigned)(d+31) <= 101
        const bool need_mask = (unsigned)(s0 + wi0 - j0 + 31) <= 101u;

        #pragma unroll
        for (int mh = 0; mh < 2; ++mh) {
            float s[2][4][4];
            #pragma unroll
            for (int mb = 0; mb < 2; ++mb)
                #pragma unroll
                for (int nb = 0; nb < 4; ++nb)
                    #pragma unroll
                    for (int r = 0; r < 4; ++r) s[mb][nb][r] = 0.f;
            #pragma unroll
            for (int ki = 0; ki < 8; ++ki) {
                unsigned af[2][4];
                #pragma unroll
                for (int mb = 0; mb < 2; ++mb) {
                    int r = mh * 32 + mb * 16;
                    af[mb][0] = Kb[(r + g) * 68 + ki * 8 + tg];
                    af[mb][1] = Kb[(r + g + 8) * 68 + ki * 8 + tg];
                    af[mb][2] = Kb[(r + g) * 68 + ki * 8 + tg + 4];
                    af[mb][3] = Kb[(r + g + 8) * 68 + ki * 8 + tg + 4];
                }
                #pragma unroll
                for (int mb = 0; mb < 2; ++mb)
                    #pragma unroll
                    for (int nb = 0; nb < 4; ++nb)
                        mma8(s[mb][nb], af[mb], qf[nb][ki]);
            }
            #pragma unroll
            for (int mb = 0; mb < 2; ++mb) {
                const int jl = mh * 32 + mb * 16 + g;
                const int jg = j0 + jl;
                #pragma unroll
                for (int nb = 0; nb < 4; ++nb) {
                    float v0 = s[mb][nb][0];
                    float v1 = s[mb][nb][1];
                    float v2 = s[mb][nb][2];
                    float v3 = s[mb][nb][3];
                    if (need_mask) {
                        const int ig = s0 + wi0 + nb * 8 + tg * 2;
                        if ((unsigned)(ig     - jg)       < 8u) v0 = -1e30f;
                        if ((unsigned)(ig + 1 - jg)       < 8u) v1 = -1e30f;
                        if ((unsigned)(ig     - (jg + 8)) < 8u) v2 = -1e30f;
                        if ((unsigned)(ig + 1 - (jg + 8)) < 8u) v3 = -1e30f;
                    }
                    float p0 = ex2f(v0);
                    float p1 = ex2f(v1);
                    float p2 = ex2f(v2);
                    float p3 = ex2f(v3);
                    l[nb][0] += p0 + p2;
                    l[nb][1] += p1 + p3;
                    const int ic = wi0 + nb * 8 + tg * 2;
                    *(uint2*)&Psu[jl * 136 + ic]       = make_uint2(f2tf(p0), f2tf(p1));
                    *(uint2*)&Psu[(jl + 8) * 136 + ic] = make_uint2(f2tf(p2), f2tf(p3));
                }
            }
        }
        __syncwarp();

        #pragma unroll
        for (int kj = 0; kj < 8; ++kj) {
            unsigned pf[4][2];
            #pragma unroll
            for (int nb = 0; nb < 4; ++nb) {
                pf[nb][0] = Psu[(kj * 8 + tg) * 136 + wi0 + nb * 8 + g];
                pf[nb][1] = Psu[(kj * 8 + tg + 4) * 136 + wi0 + nb * 8 + g];
            }
            #pragma unroll
            for (int db = 0; db < 4; ++db) {
                unsigned vf[4];
                vf[0] = Vb[(kj * 8 + tg) * 72 + db * 16 + g];
                vf[1] = Vb[(kj * 8 + tg) * 72 + db * 16 + g + 8];
                vf[2] = Vb[(kj * 8 + tg + 4) * 72 + db * 16 + g];
                vf[3] = Vb[(kj * 8 + tg + 4) * 72 + db * 16 + g + 8];
                #pragma unroll
                for (int nb = 0; nb < 4; ++nb)
                    mma8(o[db][nb], vf, pf[nb]);
            }
        }
        buf ^= 1;
    }

    #pragma unroll
    for (int nb = 0; nb < 4; ++nb) {
        #pragma unroll
        for (int c = 0; c < 2; ++c) {
            float v = l[nb][c];
            v += __shfl_xor_sync(0xffffffffu, v, 4);
            v += __shfl_xor_sync(0xffffffffu, v, 8);
            v += __shfl_xor_sync(0xffffffffu, v, 16);
            l[nb][c] = v;
        }
    }

    // epilogue: out[b][s0+wi0+i][h*64+d] = O^T[d][i] / l[i]  (tf32-rounded)
    float* ob = out + ((size_t)b * SEQ + s0 + wi0) * INNER + h * DHEAD;
    #pragma unroll
    for (int nb = 0; nb < 4; ++nb) {
        const int i0 = nb * 8 + tg * 2;
        const float inv0 = 1.f / l[nb][0];
        const float inv1 = 1.f / l[nb][1];
        #pragma unroll
        for (int db = 0; db < 4; ++db) {
            const int d0 = db * 16 + g;
            ob[(size_t)i0 * INNER + d0]           = __uint_as_float(f2tf(o[db][nb][0] * inv0));
            ob[(size_t)(i0 + 1) * INNER + d0]     = __uint_as_float(f2tf(o[db][nb][1] * inv1));
            ob[(size_t)i0 * INNER + d0 + 8]       = __uint_as_float(f2tf(o[db][nb][2] * inv0));
            ob[(size_t)(i0 + 1) * INNER + d0 + 8] = __uint_as_float(f2tf(o[db][nb][3] * inv1));
        }
    }
}

// ---------------------------------------------------------------------------
extern "C" void kernel_launch(void* const* d_in, const int* in_sizes, int n_in,
                              void* d_out, int out_size)
{
    const float* x    = (const float*)d_in[0];
    const float* Wq   = (const float*)d_in[1];
    const float* uq   = (const float*)d_in[2];
    const float* sq   = (const float*)d_in[3];
    const float* Wo   = (const float*)d_in[4];
    const float* bo   = (const float*)d_in[5];
    const float* uo   = (const float*)d_in[6];
    const float* so   = (const float*)d_in[7];
    const float* temp = (const float*)d_in[8];

    float* p_qkv  = nullptr;
    float* p_attn = nullptr;
    float* p_xr   = nullptr;
    float* p_wq   = nullptr;
    float* p_wo   = nullptr;
    cudaGetSymbolAddress((void**)&p_qkv,  g_qkv);
    cudaGetSymbolAddress((void**)&p_attn, g_attn);
    cudaGetSymbolAddress((void**)&p_xr,   g_xr);
    cudaGetSymbolAddress((void**)&p_wq,   g_wq);
    cudaGetSymbolAddress((void**)&p_wo,   g_wo);

    // pre-round operands + spectral-norm scales
    round3<<<(RN0 + RN1 + RN2) / 256, 256>>>(x, Wq, Wo);
    sn_rowdot<<<2048, 128>>>(Wq, uq, Wo, uo);
    sn_coldot<<<32, 256>>>(Wq, Wo);
    sn_scale<<<2, 256>>>(sq, so);

    const int smem_gemm = 3 * 2 * GST * (int)sizeof(float);   // 110592
    cudaFuncSetAttribute(gemm_tf32, cudaFuncAttributeMaxDynamicSharedMemorySize, smem_gemm);

    // qkv = (x @ W_qkv^T) * scale_qkv   (tf32-rounded output)
    gemm_tf32<<<dim3(QKV3 / 128, MROWS / 128), 256, smem_gemm>>>(
        p_xr, p_wq, p_qkv, MROWS, QKV3, DMODEL, 0, (const float*)nullptr, 1);

    // attention
    const int smem_attn = (2 * 64 * 68 + 2 * 64 * 72 + 64 * 136) * (int)sizeof(float); // 106496
    cudaFuncSetAttribute(attn_tf32, cudaFuncAttributeMaxDynamicSharedMemorySize, smem_attn);
    attn_tf32<<<dim3(SEQ / 128, BATCH * NHEADS), 128, smem_attn>>>(p_qkv, temp, p_attn);

    // out = (attn @ W_out^T) * scale_out + b_out
    gemm_tf32<<<dim3(DMODEL / 128, MROWS / 128), 256, smem_gemm>>>(
        p_attn, p_wo, (float*)d_out, MROWS, DMODEL, INNER, 1, bo, 0);
}

// round 7
// speedup vs baseline: 6.5774x; 1.6040x over previous
#include <cuda_runtime.h>
#include <cuda_fp16.h>
#include <math.h>

#define BATCH 2
#define SEQ   2048
#define DMODEL 512
#define NHEADS 8
#define DHEAD 64
#define INNER 512
#define QKV3  1536
#define MROWS (BATCH*SEQ)   // 4096

// Scratch (device globals; allocation is forbidden)
__device__ __half g_qk[MROWS * 1024];            // q at [r][0..511], k at [r][512..1023]
__device__ __half g_vT[BATCH * NHEADS * DHEAD * SEQ]; // [(b*8+h)*64+d][s]
__device__ __half g_attn[MROWS * INNER];         // attention out, fp16
__device__ __half g_xh[MROWS * DMODEL];
__device__ __half g_wqh[QKV3 * DMODEL];
__device__ __half g_woh[DMODEL * INNER];
__device__ float g_t[2048];
__device__ float g_part[32];
__device__ float g_scales[2];
__device__ float g_k2q;                          // exp(temperature)*log2(e)

// ---------------------------------------------------------------------------
// helpers
// ---------------------------------------------------------------------------
__device__ __forceinline__ float ex2f(float x) {
    float r;
    asm("ex2.approx.ftz.f32 %0, %1;" : "=f"(r) : "f"(x));
    return r;
}

__device__ __forceinline__ void mma16(float* c, const unsigned* a, const unsigned* b) {
    asm volatile(
        "mma.sync.aligned.m16n8k16.row.col.f32.f16.f16.f32 "
        "{%0,%1,%2,%3}, {%4,%5,%6,%7}, {%8,%9}, {%0,%1,%2,%3};"
        : "+f"(c[0]), "+f"(c[1]), "+f"(c[2]), "+f"(c[3])
        : "r"(a[0]), "r"(a[1]), "r"(a[2]), "r"(a[3]), "r"(b[0]), "r"(b[1]));
}

__device__ __forceinline__ void cpa16(unsigned dst, const void* src) {
    asm volatile("cp.async.cg.shared.global [%0], [%1], 16;" :: "r"(dst), "l"(src));
}
#define CP_COMMIT() asm volatile("cp.async.commit_group;")
#define CP_WAIT0()  asm volatile("cp.async.wait_group 0;")
#define CP_WAIT1()  asm volatile("cp.async.wait_group 1;")

// ---------------------------------------------------------------------------
// convert x / W_qkv / W_out to fp16 (8 floats per thread)
// ---------------------------------------------------------------------------
#define C0 (MROWS * DMODEL / 8)
#define C1 (QKV3 * DMODEL / 8)
#define C2 (DMODEL * INNER / 8)
__global__ __launch_bounds__(256)
void cvt_h(const float* __restrict__ x, const float* __restrict__ wq,
           const float* __restrict__ wo)
{
    int i = blockIdx.x * 256 + threadIdx.x;
    const float* src; __half* dst; int off;
    if (i < C0)           { src = x;  dst = g_xh;  off = i; }
    else if (i < C0 + C1) { src = wq; dst = g_wqh; off = i - C0; }
    else                  { src = wo; dst = g_woh; off = i - C0 - C1; }
    float4 a = ((const float4*)src)[(size_t)off * 2];
    float4 b = ((const float4*)src)[(size_t)off * 2 + 1];
    __half2 h0 = __floats2half2_rn(a.x, a.y);
    __half2 h1 = __floats2half2_rn(a.z, a.w);
    __half2 h2 = __floats2half2_rn(b.x, b.y);
    __half2 h3 = __floats2half2_rn(b.z, b.w);
    uint4 u = make_uint4(*(unsigned*)&h0, *(unsigned*)&h1, *(unsigned*)&h2, *(unsigned*)&h3);
    *(uint4*)(dst + (size_t)off * 8) = u;
}

// ---------------------------------------------------------------------------
// Spectral norm: sigma_w = ||W^T (Wu/||Wu||)||, scale = sigma_in / sigma_w
// ---------------------------------------------------------------------------
__global__ __launch_bounds__(128)
void sn_rowdot(const float* __restrict__ Wq, const float* __restrict__ uq,
               const float* __restrict__ Wo, const float* __restrict__ uo)
{
    int rb = blockIdx.x;
    const float* W; const float* u; int row;
    if (rb < 1536) { W = Wq; u = uq; row = rb; }
    else           { W = Wo; u = uo; row = rb - 1536; }
    const float* wr = W + (size_t)row * 512;
    float s = 0.f;
    for (int c = threadIdx.x; c < 512; c += 128) s += wr[c] * u[c];
    #pragma unroll
    for (int o = 16; o >= 1; o >>= 1) s += __shfl_xor_sync(0xffffffffu, s, o);
    __shared__ float red[4];
    if ((threadIdx.x & 31) == 0) red[threadIdx.x >> 5] = s;
    __syncthreads();
    if (threadIdx.x == 0) g_t[rb] = red[0] + red[1] + red[2] + red[3];
}

__global__ __launch_bounds__(256)
void sn_coldot(const float* __restrict__ Wq, const float* __restrict__ Wo)
{
    int blk = blockIdx.x;
    int w = blk >> 4;
    int cblk = blk & 15;
    const float* W = w ? Wo : Wq;
    int R = w ? 512 : 1536;
    int toff = w ? 1536 : 0;
    int dl = threadIdx.x & 31;
    int rg = threadIdx.x >> 5;
    int d = cblk * 32 + dl;
    float s = 0.f;
    for (int r = rg; r < R; r += 8) s += W[(size_t)r * 512 + d] * g_t[toff + r];
    __shared__ float red[8][33];
    red[rg][dl] = s;
    __syncthreads();
    if (rg == 0) {
        float cs = 0.f;
        #pragma unroll
        for (int q = 0; q < 8; ++q) cs += red[q][dl];
        cs = cs * cs;
        #pragma unroll
        for (int o = 16; o >= 1; o >>= 1) cs += __shfl_xor_sync(0xffffffffu, cs, o);
        if (dl == 0) g_part[blk] = cs;
    }
}

__global__ __launch_bounds__(256)
void sn_scale(const float* __restrict__ sq, const float* __restrict__ so,
              const float* __restrict__ temp)
{
    int w = blockIdx.x;
    int tid = threadIdx.x;
    float ssq = (tid < 16) ? g_part[w * 16 + tid] : 0.f;
    int R = w ? 512 : 1536;
    int off = w ? 1536 : 0;
    float tt = 0.f;
    for (int r = tid; r < R; r += 256) { float v = g_t[off + r]; tt += v * v; }
    __shared__ float ra[256], rb[256];
    ra[tid] = ssq; rb[tid] = tt;
    __syncthreads();
    for (int sft = 128; sft >= 1; sft >>= 1) {
        if (tid < sft) { ra[tid] += ra[tid + sft]; rb[tid] += rb[tid + sft]; }
        __syncthreads();
    }
    if (tid == 0) {
        float sigma_w = sqrtf(ra[0] / rb[0]);
        g_scales[w] = (w ? so[0] : sq[0]) / sigma_w;
        if (w == 0) g_k2q = expf(temp[0]) * 1.4426950408889634f;
    }
}

// ---------------------------------------------------------------------------
// fp16 GEMM: (A[M,K] @ B[N,K]^T) * g_scales[..]
// mode 0: qkv — writes g_qk (q cols pre-scaled by g_k2q) and g_vT (transposed)
// mode 1: out-proj — writes fp32 C + bias
// 256 thr / 8 warps (2x4), CTA 128x128, warp 64x32, K-step 64 halves,
// 3-stage cp.async pipeline.
// ---------------------------------------------------------------------------
#define GST (128 * 36)          // one operand stage in uints
__global__ __launch_bounds__(256, 2)
void gemm_h(const __half* __restrict__ A, const __half* __restrict__ B,
            float* __restrict__ C, int M, int N, int K,
            int mode, const float* __restrict__ bias)
{
    extern __shared__ unsigned smg[];     // [3][2*GST]
    const int t    = threadIdx.x;
    const int lane = t & 31;
    const int wid  = t >> 5;
    const int g  = lane >> 2;
    const int tg = lane & 3;
    const int wm = (wid >> 2) * 64;
    const int wn = (wid & 3) * 32;
    const int row0 = blockIdx.y * 128;
    const int col0 = blockIdx.x * 128;
    const int NK = K >> 6;                // K-step 64

    const unsigned sb = (unsigned)__cvta_generic_to_shared(smg);
    const int crow = t >> 3;              // 0..31
    const int cch  = (t & 7) * 8;         // halves offset (16B chunks)

    auto issue = [&](int st, int k0) {
        unsigned so = sb + (unsigned)(st * 2 * GST) * 4u;
        #pragma unroll
        for (int i = 0; i < 4; ++i) {
            int row = crow + i * 32;
            cpa16(so + (unsigned)(row * 36 + (t & 7) * 4) * 4u,
                  A + (size_t)(row0 + row) * K + k0 + cch);
            cpa16(so + (unsigned)(GST + row * 36 + (t & 7) * 4) * 4u,
                  B + (size_t)(col0 + row) * K + k0 + cch);
        }
    };

    issue(0, 0);  CP_COMMIT();
    issue(1, 64); CP_COMMIT();

    float acc[4][4][4];
    #pragma unroll
    for (int mi = 0; mi < 4; ++mi)
        #pragma unroll
        for (int ni = 0; ni < 4; ++ni)
            #pragma unroll
            for (int r = 0; r < 4; ++r) acc[mi][ni][r] = 0.f;

    for (int ks = 0; ks < NK; ++ks) {
        CP_WAIT1();
        __syncthreads();
        if (ks + 2 < NK) issue((ks + 2) % 3, (ks + 2) * 64);
        CP_COMMIT();

        const unsigned* Ab = smg + (ks % 3) * 2 * GST;
        const unsigned* Bb = Ab + GST;
        #pragma unroll
        for (int ki = 0; ki < 4; ++ki) {
            const int kk = ki * 8;
            unsigned af[4][4], bf[4][2];
            #pragma unroll
            for (int mi = 0; mi < 4; ++mi) {
                int r = wm + mi * 16;
                af[mi][0] = Ab[(r + g) * 36 + kk + tg];
                af[mi][1] = Ab[(r + g + 8) * 36 + kk + tg];
                af[mi][2] = Ab[(r + g) * 36 + kk + tg + 4];
                af[mi][3] = Ab[(r + g + 8) * 36 + kk + tg + 4];
            }
            #pragma unroll
            for (int ni = 0; ni < 4; ++ni) {
                int c = wn + ni * 8;
                bf[ni][0] = Bb[(c + g) * 36 + kk + tg];
                bf[ni][1] = Bb[(c + g) * 36 + kk + tg + 4];
            }
            #pragma unroll
            for (int mi = 0; mi < 4; ++mi)
                #pragma unroll
                for (int ni = 0; ni < 4; ++ni)
                    mma16(acc[mi][ni], af[mi], bf[ni]);
        }
    }

    if (mode == 0) {
        // qkv epilogue: q/k -> g_qk fp16 (q pre-scaled by k2), v -> g_vT transposed
        float scale = g_scales[0];
        if (col0 < 512) scale *= g_k2q;
        const bool is_v = (col0 >= 1024);
        #pragma unroll
        for (int mi = 0; mi < 4; ++mi) {
            int r = row0 + wm + mi * 16 + g;
            #pragma unroll
            for (int ni = 0; ni < 4; ++ni) {
                int c = col0 + wn + ni * 8 + tg * 2;
                float v0 = acc[mi][ni][0] * scale;
                float v1 = acc[mi][ni][1] * scale;
                float v2 = acc[mi][ni][2] * scale;
                float v3 = acc[mi][ni][3] * scale;
                if (!is_v) {
                    __half2 lo = __floats2half2_rn(v0, v1);
                    __half2 hi = __floats2half2_rn(v2, v3);
                    *(__half2*)&g_qk[(size_t)r * 1024 + c]       = lo;
                    *(__half2*)&g_qk[(size_t)(r + 8) * 1024 + c] = hi;
                } else {
                    int cd = c - 1024;             // h*64 + d
                    int h  = cd >> 6;
                    int d  = cd & 63;
                    int b  = r >> 11;
                    int s  = r & 2047;
                    size_t base = ((size_t)(b * 8 + h) * 64 + d) * 2048;
                    g_vT[base + s]              = __float2half_rn(v0);
                    g_vT[base + 2048 + s]       = __float2half_rn(v1);
                    g_vT[base + s + 8]          = __float2half_rn(v2);   // r+8 -> s+8
                    g_vT[base + 2048 + s + 8]   = __float2half_rn(v3);
                }
            }
        }
    } else {
        const float scale = g_scales[1];
        #pragma unroll
        for (int mi = 0; mi < 4; ++mi) {
            int r = row0 + wm + mi * 16 + g;
            #pragma unroll
            for (int ni = 0; ni < 4; ++ni) {
                int c = col0 + wn + ni * 8 + tg * 2;
                float b0 = bias[c], b1 = bias[c + 1];
                *(float2*)&C[(size_t)r * N + c] =
                    make_float2(acc[mi][ni][0] * scale + b0, acc[mi][ni][1] * scale + b1);
                *(float2*)&C[(size_t)(r + 8) * N + c] =
                    make_float2(acc[mi][ni][2] * scale + b0, acc[mi][ni][3] * scale + b1);
            }
        }
    }
}

// ---------------------------------------------------------------------------
// fp16 flash attention (no-max; logits bounded; Q pre-scaled in gemm epilogue).
// 128 thr / 4 warps, Bq=128 (warp w owns query cols w*32..+31), Bk=64.
// S^T = K @ Q^T (m=j, n=i, k=d), O^T = V^T @ P^T (m=d, n=i, k=j).
// V arrives pre-transposed from g_vT. 2-stage cp.async K/V pipeline.
// ---------------------------------------------------------------------------
#define KOFFU(buf) ((buf) * (64 * 36))
#define VOFFU(buf) (2 * 64 * 36 + (buf) * (64 * 36))
#define POFFU      (4 * 64 * 36)

__global__ __launch_bounds__(128, 2)
void attn_h(__half* __restrict__ out)
{
    extern __shared__ unsigned sma[];     // K[2][64*36] VT[2][64*36] P/Q[128*36]
    const int t    = threadIdx.x;
    const int lane = t & 31;
    const int w    = t >> 5;
    const int g    = lane >> 2;
    const int tg   = lane & 3;
    const int bh = blockIdx.y;
    const int b  = bh >> 3;
    const int h  = bh & 7;
    const int s0 = blockIdx.x * 128;
    const int wi0 = w * 32;

    const __half* qbase = g_qk + ((size_t)(b * SEQ + s0)) * 1024 + h * 64;
    const __half* kbase = g_qk + (size_t)b * SEQ * 1024 + 512 + h * 64;
    const __half* vbase = g_vT + (size_t)(b * 8 + h) * 64 * 2048;

    const unsigned sb = (unsigned)__cvta_generic_to_shared(sma);
    const int lrow = t >> 3;         // 0..15
    const int lch  = (t & 7);        // 16B chunk

    auto issueKV = [&](int buf, int j0) {
        #pragma unroll
        for (int i = 0; i < 4; ++i) {
            int row = lrow + i * 16;
            cpa16(sb + (unsigned)(KOFFU(buf) + row * 36 + lch * 4) * 4u,
                  kbase + (size_t)(j0 + row) * 1024 + lch * 8);
            cpa16(sb + (unsigned)(VOFFU(buf) + row * 36 + lch * 4) * 4u,
                  vbase + (size_t)row * 2048 + j0 + lch * 8);
        }
    };

    issueKV(0, 0); CP_COMMIT();
    // stage Q [128][64] halves
    #pragma unroll
    for (int i = 0; i < 8; ++i) {
        int row = lrow + i * 16;
        cpa16(sb + (unsigned)(POFFU + row * 36 + lch * 4) * 4u,
              qbase + (size_t)row * 1024 + lch * 8);
    }
    CP_COMMIT();
    CP_WAIT0();
    __syncthreads();

    const unsigned* Pu = sma + POFFU;
    unsigned qf[4][4][2];
    #pragma unroll
    for (int nb = 0; nb < 4; ++nb)
        #pragma unroll
        for (int ki = 0; ki < 4; ++ki) {
            qf[nb][ki][0] = Pu[(wi0 + nb * 8 + g) * 36 + ki * 8 + tg];
            qf[nb][ki][1] = Pu[(wi0 + nb * 8 + g) * 36 + ki * 8 + tg + 4];
        }
    __half* Ph = (__half*)(sma + POFFU);

    float o[4][4][4];
    #pragma unroll
    for (int db = 0; db < 4; ++db)
        #pragma unroll
        for (int nb = 0; nb < 4; ++nb)
            #pragma unroll
            for (int r = 0; r < 4; ++r) o[db][nb][r] = 0.f;
    float l[4][2];
    #pragma unroll
    for (int nb = 0; nb < 4; ++nb) { l[nb][0] = 0.f; l[nb][1] = 0.f; }

    int buf = 0;
    for (int kt = 0; kt < SEQ / 64; ++kt) {
        __syncthreads();
        if (kt + 1 < SEQ / 64) issueKV(buf ^ 1, (kt + 1) * 64);
        CP_COMMIT();
        CP_WAIT1();
        __syncthreads();

        const unsigned* Kb = sma + KOFFU(buf);
        const unsigned* Vb = sma + VOFFU(buf);
        const int j0 = kt * 64;
        const bool need_mask = (unsigned)(s0 + wi0 - j0 + 31) <= 101u;

        // S^T = K @ Q^T in two 32-row (j) halves; softmax fused
        #pragma unroll
        for (int mh = 0; mh < 2; ++mh) {
            float s[2][4][4];
            #pragma unroll
            for (int mb = 0; mb < 2; ++mb)
                #pragma unroll
                for (int nb = 0; nb < 4; ++nb)
                    #pragma unroll
                    for (int r = 0; r < 4; ++r) s[mb][nb][r] = 0.f;
            #pragma unroll
            for (int ki = 0; ki < 4; ++ki) {
                unsigned af[2][4];
                #pragma unroll
                for (int mb = 0; mb < 2; ++mb) {
                    int r = mh * 32 + mb * 16;
                    af[mb][0] = Kb[(r + g) * 36 + ki * 8 + tg];
                    af[mb][1] = Kb[(r + g + 8) * 36 + ki * 8 + tg];
                    af[mb][2] = Kb[(r + g) * 36 + ki * 8 + tg + 4];
                    af[mb][3] = Kb[(r + g + 8) * 36 + ki * 8 + tg + 4];
                }
                #pragma unroll
                for (int mb = 0; mb < 2; ++mb)
                    #pragma unroll
                    for (int nb = 0; nb < 4; ++nb)
                        mma16(s[mb][nb], af[mb], qf[nb][ki]);
            }
            #pragma unroll
            for (int mb = 0; mb < 2; ++mb) {
                const int jl = mh * 32 + mb * 16 + g;
                const int jg = j0 + jl;
                #pragma unroll
                for (int nb = 0; nb < 4; ++nb) {
                    const int i0 = wi0 + nb * 8 + tg * 2;
                    float v0 = s[mb][nb][0];
                    float v1 = s[mb][nb][1];
                    float v2 = s[mb][nb][2];
                    float v3 = s[mb][nb][3];
                    if (need_mask) {
                        const int ig = s0 + i0;
                        if ((unsigned)(ig     - jg)       < 8u) v0 = -1e30f;
                        if ((unsigned)(ig + 1 - jg)       < 8u) v1 = -1e30f;
                        if ((unsigned)(ig     - (jg + 8)) < 8u) v2 = -1e30f;
                        if ((unsigned)(ig + 1 - (jg + 8)) < 8u) v3 = -1e30f;
                    }
                    float p0 = ex2f(v0);
                    float p1 = ex2f(v1);
                    float p2 = ex2f(v2);
                    float p3 = ex2f(v3);
                    l[nb][0] += p0 + p2;
                    l[nb][1] += p1 + p3;
                    Ph[(i0)     * 72 + jl]     = __float2half_rn(p0);
                    Ph[(i0 + 1) * 72 + jl]     = __float2half_rn(p1);
                    Ph[(i0)     * 72 + jl + 8] = __float2half_rn(p2);
                    Ph[(i0 + 1) * 72 + jl + 8] = __float2half_rn(p3);
                }
            }
        }
        __syncwarp();   // P stripe produced & consumed within the same warp

        // O^T += V^T @ P^T
        #pragma unroll
        for (int kj = 0; kj < 4; ++kj) {
            unsigned pf[4][2];
            #pragma unroll
            for (int nb = 0; nb < 4; ++nb) {
                pf[nb][0] = Pu[(wi0 + nb * 8 + g) * 36 + kj * 8 + tg];
                pf[nb][1] = Pu[(wi0 + nb * 8 + g) * 36 + kj * 8 + tg + 4];
            }
            #pragma unroll
            for (int db = 0; db < 4; ++db) {
                unsigned vf[4];
                vf[0] = Vb[(db * 16 + g) * 36 + kj * 8 + tg];
                vf[1] = Vb[(db * 16 + g + 8) * 36 + kj * 8 + tg];
                vf[2] = Vb[(db * 16 + g) * 36 + kj * 8 + tg + 4];
                vf[3] = Vb[(db * 16 + g + 8) * 36 + kj * 8 + tg + 4];
                #pragma unroll
                for (int nb = 0; nb < 4; ++nb)
                    mma16(o[db][nb], vf, pf[nb]);
            }
        }
        buf ^= 1;
    }

    // finish column sums (reduce over g lanes)
    #pragma unroll
    for (int nb = 0; nb < 4; ++nb) {
        #pragma unroll
        for (int c = 0; c < 2; ++c) {
            float v = l[nb][c];
            v += __shfl_xor_sync(0xffffffffu, v, 4);
            v += __shfl_xor_sync(0xffffffffu, v, 8);
            v += __shfl_xor_sync(0xffffffffu, v, 16);
            l[nb][c] = v;
        }
    }

    // epilogue: g_attn[b][s0+i][h*64+d] = O^T[d][i] / l[i]  (fp16)
    __half* ob = out + ((size_t)(b * SEQ + s0 + wi0)) * INNER + h * DHEAD;
    #pragma unroll
    for (int nb = 0; nb < 4; ++nb) {
        const int i0 = nb * 8 + tg * 2;
        const float inv0 = 1.f / l[nb][0];
        const float inv1 = 1.f / l[nb][1];
        #pragma unroll
        for (int db = 0; db < 4; ++db) {
            const int d0 = db * 16 + g;
            ob[(size_t)i0 * INNER + d0]           = __float2half_rn(o[db][nb][0] * inv0);
            ob[(size_t)(i0 + 1) * INNER + d0]     = __float2half_rn(o[db][nb][1] * inv1);
            ob[(size_t)i0 * INNER + d0 + 8]       = __float2half_rn(o[db][nb][2] * inv0);
            ob[(size_t)(i0 + 1) * INNER + d0 + 8] = __float2half_rn(o[db][nb][3] * inv1);
        }
    }
}

// ---------------------------------------------------------------------------
extern "C" void kernel_launch(void* const* d_in, const int* in_sizes, int n_in,
                              void* d_out, int out_size)
{
    const float* x    = (const float*)d_in[0];
    const float* Wq   = (const float*)d_in[1];
    const float* uq   = (const float*)d_in[2];
    const float* sq   = (const float*)d_in[3];
    const float* Wo   = (const float*)d_in[4];
    const float* bo   = (const float*)d_in[5];
    const float* uo   = (const float*)d_in[6];
    const float* so   = (const float*)d_in[7];
    const float* temp = (const float*)d_in[8];

    __half* p_xh  = nullptr; __half* p_wqh = nullptr; __half* p_woh = nullptr;
    __half* p_attn = nullptr;
    cudaGetSymbolAddress((void**)&p_xh,   g_xh);
    cudaGetSymbolAddress((void**)&p_wqh,  g_wqh);
    cudaGetSymbolAddress((void**)&p_woh,  g_woh);
    cudaGetSymbolAddress((void**)&p_attn, g_attn);

    cvt_h<<<(C0 + C1 + C2) / 256, 256>>>(x, Wq, Wo);
    sn_rowdot<<<2048, 128>>>(Wq, uq, Wo, uo);
    sn_coldot<<<32, 256>>>(Wq, Wo);
    sn_scale<<<2, 256>>>(sq, so, temp);

    const int smem_gemm = 3 * 2 * GST * (int)sizeof(unsigned);   // 110592
    cudaFuncSetAttribute(gemm_h, cudaFuncAttributeMaxDynamicSharedMemorySize, smem_gemm);

    // qkv projection (writes g_qk + g_vT internally)
    gemm_h<<<dim3(QKV3 / 128, MROWS / 128), 256, smem_gemm>>>(
        p_xh, p_wqh, nullptr, MROWS, QKV3, DMODEL, 0, nullptr);

    // attention
    const int smem_attn = (4 * 64 * 36 + 128 * 36) * (int)sizeof(unsigned); // 55296
    cudaFuncSetAttribute(attn_h, cudaFuncAttributeMaxDynamicSharedMemorySize, smem_attn);
    attn_h<<<dim3(SEQ / 128, BATCH * NHEADS), 128, smem_attn>>>(p_attn);

    // out = (attn @ W_out^T) * scale_out + b_out
    gemm_h<<<dim3(DMODEL / 128, MROWS / 128), 256, smem_gemm>>>(
        p_attn, p_woh, (float*)d_out, MROWS, DMODEL, INNER, 1, bo);
}